// round 4
// baseline (speedup 1.0000x reference)
#include <cuda_runtime.h>
#include <cstdint>
#include <cstddef>

#define S_LEN  4096
#define DMODEL 2048
#define NHEADS 16
#define HDIM   128

// Scratch (static device memory — allowed; runtime alloc is not)
__device__ float g_Q[S_LEN * DMODEL];
__device__ float g_K[S_LEN * DMODEL];
__device__ float g_V[S_LEN * DMODEL];
__device__ float g_ctx[S_LEN * DMODEL];

// ---------------- packed f32x2 helpers (Blackwell FFMA2) ----------------
__device__ __forceinline__ void fma2(unsigned long long& d,
                                     unsigned long long a,
                                     unsigned long long b) {
    asm("fma.rn.f32x2 %0, %1, %2, %0;" : "+l"(d) : "l"(a), "l"(b));
}
__device__ __forceinline__ void mul2(unsigned long long& d, unsigned long long a) {
    asm("mul.rn.f32x2 %0, %0, %1;" : "+l"(d) : "l"(a));
}
__device__ __forceinline__ unsigned long long pack2(float lo, float hi) {
    unsigned long long r;
    asm("mov.b64 %0, {%1, %2};" : "=l"(r) : "f"(lo), "f"(hi));
    return r;
}
__device__ __forceinline__ float2 unpack2(unsigned long long v) {
    float2 r;
    asm("mov.b64 {%0, %1}, %2;" : "=f"(r.x), "=f"(r.y) : "l"(v));
    return r;
}

// ---------------------------------------------------------------------------
// GEMM (NT): C[M,N] = A[M,K] * B[N,K]^T + bias[N]
// Block 128x128, K-tile 16, 256 threads, strided 8x8 register tile.
// f32x2 accumulators pair over K (even K in lo, odd K in hi; final add).
// ---------------------------------------------------------------------------
__global__ __launch_bounds__(256, 1)
void gemm_nt_bias(const float* __restrict__ A, const float* __restrict__ B,
                  const float* __restrict__ bias, float* __restrict__ C,
                  int M, int N, int K)
{
    __shared__ __align__(16) float As[128][20];
    __shared__ __align__(16) float Bs[128][20];

    const int tid = threadIdx.x;
    const int tx = tid & 15, ty = tid >> 4;
    const int m0 = blockIdx.y * 128, n0 = blockIdx.x * 128;

    // loader: each thread owns 2 rows (lrow, lrow+64), one float4 (16B) of K per row
    const int lrow = tid >> 2;
    const int lk   = (tid & 3) * 4;
    const float* Ap = A + (size_t)(m0 + lrow) * K + lk;
    const float* Bp = B + (size_t)(n0 + lrow) * K + lk;
    const size_t rstep = (size_t)64 * K;

    float4 pa0 = *(const float4*)(Ap);
    float4 pa1 = *(const float4*)(Ap + rstep);
    float4 pb0 = *(const float4*)(Bp);
    float4 pb1 = *(const float4*)(Bp + rstep);

    unsigned long long acc[8][8];
#pragma unroll
    for (int i = 0; i < 8; i++)
#pragma unroll
        for (int j = 0; j < 8; j++) acc[i][j] = 0ull;

    const int ntiles = K >> 4;
    for (int t = 0; t < ntiles; ++t) {
        *(float4*)&As[lrow][lk]      = pa0;
        *(float4*)&As[lrow + 64][lk] = pa1;
        *(float4*)&Bs[lrow][lk]      = pb0;
        *(float4*)&Bs[lrow + 64][lk] = pb1;
        __syncthreads();

        if (t + 1 < ntiles) {
            const float* An = Ap + (size_t)(t + 1) * 16;
            const float* Bn = Bp + (size_t)(t + 1) * 16;
            pa0 = *(const float4*)(An);
            pa1 = *(const float4*)(An + rstep);
            pb0 = *(const float4*)(Bn);
            pb1 = *(const float4*)(Bn + rstep);
        }

#pragma unroll
        for (int kk = 0; kk < 16; kk += 2) {
            unsigned long long a[8], b[8];
#pragma unroll
            for (int i = 0; i < 8; i++)
                a[i] = *(const unsigned long long*)&As[ty + 16 * i][kk];
#pragma unroll
            for (int j = 0; j < 8; j++)
                b[j] = *(const unsigned long long*)&Bs[tx + 16 * j][kk];
#pragma unroll
            for (int i = 0; i < 8; i++)
#pragma unroll
                for (int j = 0; j < 8; j++)
                    fma2(acc[i][j], a[i], b[j]);
        }
        __syncthreads();
    }

#pragma unroll
    for (int j = 0; j < 8; j++) {
        const int col = n0 + tx + 16 * j;
        const float bj = bias[col];
#pragma unroll
        for (int i = 0; i < 8; i++) {
            const int row = m0 + ty + 16 * i;
            float2 v = unpack2(acc[i][j]);
            C[(size_t)row * N + col] = v.x + v.y + bj;
        }
    }
}

// ---------------------------------------------------------------------------
// Flash attention (non-causal), fp32. Per block: 128 query rows, one head.
// Key loop in tiles of 64. 256 threads = 16x16; thread rows r=ty+16i (8),
// QK cols c=tx+16j (4), PV cols n=2*tx+32n2 (4 float2 pairs = 8).
// ---------------------------------------------------------------------------
#define Q_ROWS 128
#define K_ROWS 64
// smem carve (floats): Qs[128][132] | Ks[64][132] | Vs[64][132] | Ps[128][128]
#define OFF_KS (128 * 132)
#define OFF_VS (128 * 132 + 64 * 132)
#define OFF_PS (128 * 132 + 2 * 64 * 132)
#define ATT_SMEM_BYTES ((128 * 132 + 2 * 64 * 132 + 128 * 128) * 4)

__global__ __launch_bounds__(256, 1)
void attn_kernel(const float* __restrict__ Q, const float* __restrict__ K,
                 const float* __restrict__ V, float* __restrict__ ctx)
{
    extern __shared__ __align__(16) float sm[];
    float (*Qs)[132] = (float (*)[132])sm;
    float (*Ks)[132] = (float (*)[132])(sm + OFF_KS);
    float (*Vs)[132] = (float (*)[132])(sm + OFF_VS);
    float (*Ps)[128] = (float (*)[128])(sm + OFF_PS);

    const int tid = threadIdx.x;
    const int tx = tid & 15, ty = tid >> 4;
    const int qb = blockIdx.x;   // 0..31
    const int h  = blockIdx.y;   // 0..15

    const float* Qg = Q + (size_t)(qb * Q_ROWS) * DMODEL + h * HDIM;
    const float* Kg = K + (size_t)h * HDIM;
    const float* Vg = V + (size_t)h * HDIM;

    const float qscale = 0.08838834764831845f;  // 1/sqrt(128)

    // load Q tile once, pre-scaled
    for (int f = tid; f < Q_ROWS * 32; f += 256) {
        int row = f >> 5;
        int c = (f & 31) << 2;
        float4 v = *(const float4*)(Qg + (size_t)row * DMODEL + c);
        v.x *= qscale; v.y *= qscale; v.z *= qscale; v.w *= qscale;
        *(float4*)&Qs[row][c] = v;
    }

    unsigned long long o[8][4];
#pragma unroll
    for (int i = 0; i < 8; i++)
#pragma unroll
        for (int n = 0; n < 4; n++) o[i][n] = 0ull;
    float mrow[8], lrow[8];
#pragma unroll
    for (int i = 0; i < 8; i++) { mrow[i] = -1e30f; lrow[i] = 0.f; }

    for (int kt = 0; kt < S_LEN / K_ROWS; ++kt) {
        __syncthreads();  // previous PV must be done with Ks/Vs/Ps
        for (int f = tid; f < K_ROWS * 32; f += 256) {
            int row = f >> 5;
            int c = (f & 31) << 2;
            size_t g = (size_t)(kt * K_ROWS + row) * DMODEL + c;
            *(float4*)&Ks[row][c] = *(const float4*)(Kg + g);
            *(float4*)&Vs[row][c] = *(const float4*)(Vg + g);
        }
        __syncthreads();

        // ---- S = (Q*scale) K^T, paired over kk ----
        unsigned long long s2[8][4];
#pragma unroll
        for (int i = 0; i < 8; i++)
#pragma unroll
            for (int j = 0; j < 4; j++) s2[i][j] = 0ull;

#pragma unroll 2
        for (int kk = 0; kk < HDIM; kk += 4) {
            ulonglong2 a[8], b[4];
#pragma unroll
            for (int i = 0; i < 8; i++)
                a[i] = *(const ulonglong2*)&Qs[ty + 16 * i][kk];
#pragma unroll
            for (int j = 0; j < 4; j++)
                b[j] = *(const ulonglong2*)&Ks[tx + 16 * j][kk];
#pragma unroll
            for (int i = 0; i < 8; i++)
#pragma unroll
                for (int j = 0; j < 4; j++) {
                    fma2(s2[i][j], a[i].x, b[j].x);
                    fma2(s2[i][j], a[i].y, b[j].y);
                }
        }

        // ---- online softmax, write duplicated P to smem ----
#pragma unroll
        for (int i = 0; i < 8; i++) {
            float s[4];
#pragma unroll
            for (int j = 0; j < 4; j++) {
                float2 v = unpack2(s2[i][j]);
                s[j] = v.x + v.y;
            }
            float mx = fmaxf(fmaxf(s[0], s[1]), fmaxf(s[2], s[3]));
            mx = fmaxf(mx, __shfl_xor_sync(0xffffffffu, mx, 1));
            mx = fmaxf(mx, __shfl_xor_sync(0xffffffffu, mx, 2));
            mx = fmaxf(mx, __shfl_xor_sync(0xffffffffu, mx, 4));
            mx = fmaxf(mx, __shfl_xor_sync(0xffffffffu, mx, 8));
            float mnew  = fmaxf(mrow[i], mx);
            float alpha = __expf(mrow[i] - mnew);
            mrow[i] = mnew;
            float rs = 0.f;
            const int r = ty + 16 * i;
#pragma unroll
            for (int j = 0; j < 4; j++) {
                float p = __expf(s[j] - mnew);
                rs += p;
                *(float2*)&Ps[r][2 * (tx + 16 * j)] = make_float2(p, p);
            }
            lrow[i] = lrow[i] * alpha + rs;
            unsigned long long al2 = pack2(alpha, alpha);
#pragma unroll
            for (int n = 0; n < 4; n++) mul2(o[i][n], al2);
        }
        __syncthreads();

        // ---- O += P V  (pairs over output columns; no final split) ----
#pragma unroll 2
        for (int c = 0; c < K_ROWS; c += 2) {
            ulonglong2 p[8];
            unsigned long long va[4], vb[4];
#pragma unroll
            for (int i = 0; i < 8; i++)
                p[i] = *(const ulonglong2*)&Ps[ty + 16 * i][2 * c];
#pragma unroll
            for (int n = 0; n < 4; n++) {
                va[n] = *(const unsigned long long*)&Vs[c][2 * tx + 32 * n];
                vb[n] = *(const unsigned long long*)&Vs[c + 1][2 * tx + 32 * n];
            }
#pragma unroll
            for (int i = 0; i < 8; i++)
#pragma unroll
                for (int n = 0; n < 4; n++) {
                    fma2(o[i][n], p[i].x, va[n]);
                    fma2(o[i][n], p[i].y, vb[n]);
                }
        }
    }

    // ---- finalize: normalize by row sum, store ctx ----
#pragma unroll
    for (int i = 0; i < 8; i++) {
        float l = lrow[i];
        l += __shfl_xor_sync(0xffffffffu, l, 1);
        l += __shfl_xor_sync(0xffffffffu, l, 2);
        l += __shfl_xor_sync(0xffffffffu, l, 4);
        l += __shfl_xor_sync(0xffffffffu, l, 8);
        float inv = 1.f / l;
        int row = qb * Q_ROWS + ty + 16 * i;
        float* outp = ctx + (size_t)row * DMODEL + h * HDIM;
#pragma unroll
        for (int n = 0; n < 4; n++) {
            float2 v = unpack2(o[i][n]);
            v.x *= inv; v.y *= inv;
            *(float2*)&outp[2 * tx + 32 * n] = v;
        }
    }
}

// ---------------------------------------------------------------------------
extern "C" void kernel_launch(void* const* d_in, const int* in_sizes, int n_in,
                              void* d_out, int out_size)
{
    (void)in_sizes; (void)n_in; (void)out_size;
    const float* x  = (const float*)d_in[0];
    const float* Wq = (const float*)d_in[1];
    const float* bq = (const float*)d_in[2];
    const float* Wk = (const float*)d_in[3];
    const float* bk = (const float*)d_in[4];
    const float* Wv = (const float*)d_in[5];
    const float* bv = (const float*)d_in[6];
    const float* Wo = (const float*)d_in[7];
    const float* bo = (const float*)d_in[8];
    float* out = (float*)d_out;

    float *Qb, *Kb, *Vb, *Cb;
    cudaGetSymbolAddress((void**)&Qb, g_Q);
    cudaGetSymbolAddress((void**)&Kb, g_K);
    cudaGetSymbolAddress((void**)&Vb, g_V);
    cudaGetSymbolAddress((void**)&Cb, g_ctx);

    cudaFuncSetAttribute(attn_kernel, cudaFuncAttributeMaxDynamicSharedMemorySize,
                         ATT_SMEM_BYTES);

    dim3 gThr(256);
    dim3 gGemm(DMODEL / 128, S_LEN / 128);   // (16, 32)

    gemm_nt_bias<<<gGemm, gThr>>>(x, Wq, bq, Qb, S_LEN, DMODEL, DMODEL);
    gemm_nt_bias<<<gGemm, gThr>>>(x, Wk, bk, Kb, S_LEN, DMODEL, DMODEL);
    gemm_nt_bias<<<gGemm, gThr>>>(x, Wv, bv, Vb, S_LEN, DMODEL, DMODEL);

    dim3 gAttn(S_LEN / Q_ROWS, NHEADS);      // (32, 16)
    attn_kernel<<<gAttn, gThr, ATT_SMEM_BYTES>>>(Qb, Kb, Vb, Cb);

    gemm_nt_bias<<<gGemm, gThr>>>(Cb, Wo, bo, out, S_LEN, DMODEL, DMODEL);
}

// round 8
// speedup vs baseline: 2.1311x; 2.1311x over previous
#include <cuda_runtime.h>
#include <cuda_bf16.h>
#include <cstdint>
#include <cstddef>

typedef __nv_bfloat16 bf16;

#define S_LEN  4096
#define DMODEL 2048
#define NHEADS 16
#define HDIM   128

constexpr size_t SD  = (size_t)S_LEN * DMODEL;     // 8,388,608
constexpr size_t DD  = (size_t)DMODEL * DMODEL;    // 4,194,304
constexpr size_t SSQ = (size_t)S_LEN * S_LEN;      // 16,777,216
constexpr size_t HS2 = (size_t)NHEADS * SSQ;       // 268,435,456

// ---------------- static device scratch (no runtime alloc allowed) ----------
// g_S holds fp32 scores, then is overwritten IN PLACE by softmax with the
// bf16 hi/lo split of P: row r bf16 units [0,4096) = Phi, [4096,8192) = Plo.
__device__ float g_Q[SD];
__device__ float g_K[SD];
__device__ float g_V[SD];
__device__ float g_ctx[SD];
__device__ float g_S[HS2];                 // scores / P storage, 1 GB
__device__ bf16  g_xh[SD],  g_xl[SD];
__device__ bf16  g_wqh[DD], g_wql[DD], g_wkh[DD], g_wkl[DD];
__device__ bf16  g_wvh[DD], g_wvl[DD], g_woh[DD], g_wol[DD];
__device__ bf16  g_qh[SD],  g_ql[SD];      // Q pre-scaled by 1/sqrt(Hd)
__device__ bf16  g_kh[SD],  g_kl[SD];
__device__ bf16  g_vth[SD], g_vtl[SD];     // V^T  [DMODEL][S_LEN]
__device__ bf16  g_ch[SD],  g_cl[SD];

// ---------------- baseline-PTX helpers (sm_80+, no 'a' features) ------------
__device__ __forceinline__ void cpasync16(void* dst, const void* src) {
    uint32_t d = (uint32_t)__cvta_generic_to_shared(dst);
    asm volatile("cp.async.cg.shared.global [%0], [%1], 16;" :: "r"(d), "l"(src));
}
__device__ __forceinline__ void cp_commit() {
    asm volatile("cp.async.commit_group;" ::: "memory");
}
__device__ __forceinline__ void cp_wait_all() {
    asm volatile("cp.async.wait_group 0;" ::: "memory");
}
// m16n8k16 row.col bf16 -> fp32 accumulate
__device__ __forceinline__ void mma16816(float* d, const uint32_t* a, const uint32_t* b) {
    asm volatile(
        "mma.sync.aligned.m16n8k16.row.col.f32.bf16.bf16.f32 "
        "{%0,%1,%2,%3}, {%4,%5,%6,%7}, {%8,%9}, {%0,%1,%2,%3};"
        : "+f"(d[0]), "+f"(d[1]), "+f"(d[2]), "+f"(d[3])
        : "r"(a[0]), "r"(a[1]), "r"(a[2]), "r"(a[3]), "r"(b[0]), "r"(b[1]));
}

// ---------------------------------------------------------------------------
// Generic bf16x3 GEMM: C[M,N] = (Ahi+Alo)[M,K] * (Bhi+Blo)[N,K]^T (+ bias)
// fp32 accumulation in registers via mma.sync (HMMA).
// BM=128, BN=128, BK=32, 256 threads, 8 warps in 4(m) x 2(n), warp tile 32x64.
// grid.z slices via zA/zB/zC element offsets.
// ---------------------------------------------------------------------------
#define BM 128
#define BN 128
#define BK 32
#define ROWE   40                      // smem row stride in bf16 (32 + 8 pad)
#define SUB_B  (128 * ROWE * 2)        // one subtile: 10240 bytes
#define BUF_B  (4 * SUB_B)             // Ahi|Alo|Bhi|Blo = 40960 bytes
#define GEMM_SMEM (2 * BUF_B)          // double buffer: 81920 bytes

__global__ __launch_bounds__(256, 1)
void gemm_bf16x3(const bf16* __restrict__ Ahi, const bf16* __restrict__ Alo,
                 const bf16* __restrict__ Bhi, const bf16* __restrict__ Blo,
                 const float* __restrict__ bias, float* __restrict__ C,
                 int K, int lda, int ldb, int ldc,
                 size_t zA, size_t zB, size_t zC)
{
    extern __shared__ char smc[];
    const int tid = threadIdx.x;
    const int wid = tid >> 5, l = tid & 31;
    const int gr = l >> 2, kc = (l & 3) * 2;
    const int warp_m = wid & 3, warp_n = wid >> 2;
    const int n0 = blockIdx.x * BN, m0 = blockIdx.y * BM;
    const size_t z = blockIdx.z;
    Ahi += z * zA; Alo += z * zA; Bhi += z * zB; Blo += z * zB; C += z * zC;

    float acc[2][8][4];
#pragma unroll
    for (int mt = 0; mt < 2; mt++)
#pragma unroll
        for (int nt = 0; nt < 8; nt++)
#pragma unroll
            for (int i = 0; i < 4; i++) acc[mt][nt][i] = 0.f;

    // one subtile = 128 rows x 32 bf16 = 512 x 16B chunks; 256 thr x 2 chunks
    auto load_sub = [&](char* dstbase, const bf16* src, int row0, int ld, int k0) {
#pragma unroll
        for (int i = 0; i < 2; i++) {
            int c = tid + 256 * i;
            int row = c >> 2, col = (c & 3) * 8;       // col in bf16 units
            cpasync16(dstbase + row * (ROWE * 2) + col * 2,
                      src + (size_t)(row0 + row) * ld + k0 + col);
        }
    };
    auto load_tile = [&](int t, int b) {
        char* base = smc + b * BUF_B;
        int k0 = t * BK;
        load_sub(base,             Ahi, m0, lda, k0);
        load_sub(base + SUB_B,     Alo, m0, lda, k0);
        load_sub(base + 2 * SUB_B, Bhi, n0, ldb, k0);
        load_sub(base + 3 * SUB_B, Blo, n0, ldb, k0);
        cp_commit();
    };

    const int T = K / BK;
    load_tile(0, 0);
    for (int t = 0; t < T; t++) {
        const int b = t & 1;
        cp_wait_all();
        __syncthreads();
        if (t + 1 < T) load_tile(t + 1, 1 ^ b);   // overlap next loads w/ MMA

        const char* base = smc + b * BUF_B;
        const bf16* sAh = (const bf16*)(base);
        const bf16* sAl = (const bf16*)(base + SUB_B);
        const bf16* sBh = (const bf16*)(base + 2 * SUB_B);
        const bf16* sBl = (const bf16*)(base + 3 * SUB_B);

#pragma unroll
        for (int ks = 0; ks < 2; ks++) {
            const int kb = ks * 16 + kc;
            uint32_t ah[2][4], al[2][4];
#pragma unroll
            for (int mt = 0; mt < 2; mt++) {
                const int r = warp_m * 32 + mt * 16 + gr;
                ah[mt][0] = *(const uint32_t*)&sAh[(r)     * ROWE + kb];
                ah[mt][1] = *(const uint32_t*)&sAh[(r + 8) * ROWE + kb];
                ah[mt][2] = *(const uint32_t*)&sAh[(r)     * ROWE + kb + 8];
                ah[mt][3] = *(const uint32_t*)&sAh[(r + 8) * ROWE + kb + 8];
                al[mt][0] = *(const uint32_t*)&sAl[(r)     * ROWE + kb];
                al[mt][1] = *(const uint32_t*)&sAl[(r + 8) * ROWE + kb];
                al[mt][2] = *(const uint32_t*)&sAl[(r)     * ROWE + kb + 8];
                al[mt][3] = *(const uint32_t*)&sAl[(r + 8) * ROWE + kb + 8];
            }
            uint32_t bh[8][2], bl[8][2];
#pragma unroll
            for (int nt = 0; nt < 8; nt++) {
                const int n = warp_n * 64 + nt * 8 + gr;
                bh[nt][0] = *(const uint32_t*)&sBh[n * ROWE + kb];
                bh[nt][1] = *(const uint32_t*)&sBh[n * ROWE + kb + 8];
                bl[nt][0] = *(const uint32_t*)&sBl[n * ROWE + kb];
                bl[nt][1] = *(const uint32_t*)&sBl[n * ROWE + kb + 8];
            }
#pragma unroll
            for (int mt = 0; mt < 2; mt++)
#pragma unroll
                for (int nt = 0; nt < 8; nt++) {
                    mma16816(acc[mt][nt], ah[mt], bh[nt]);   // hi*hi
                    mma16816(acc[mt][nt], ah[mt], bl[nt]);   // hi*lo
                    mma16816(acc[mt][nt], al[mt], bh[nt]);   // lo*hi
                }
        }
        __syncthreads();
    }

    // epilogue: c0,c1 -> row r cols (c,c+1); c2,c3 -> row r+8
#pragma unroll
    for (int nt = 0; nt < 8; nt++) {
        const int c = n0 + warp_n * 64 + nt * 8 + kc;
        float2 bv = make_float2(0.f, 0.f);
        if (bias) bv = *(const float2*)&bias[c];
#pragma unroll
        for (int mt = 0; mt < 2; mt++) {
            const int r = m0 + warp_m * 32 + mt * 16 + gr;
            float2 v0 = make_float2(acc[mt][nt][0] + bv.x, acc[mt][nt][1] + bv.y);
            float2 v1 = make_float2(acc[mt][nt][2] + bv.x, acc[mt][nt][3] + bv.y);
            *(float2*)&C[(size_t)r * ldc + c]       = v0;
            *(float2*)&C[(size_t)(r + 8) * ldc + c] = v1;
        }
    }
}

// ---------------------------------------------------------------------------
// fp32 -> (hi, lo) bf16 split, optional scale folded in
// ---------------------------------------------------------------------------
__global__ __launch_bounds__(256)
void split_kernel(const float* __restrict__ in, bf16* __restrict__ hi,
                  bf16* __restrict__ lo, float scale, size_t n)
{
    size_t i = ((size_t)blockIdx.x * 256 + threadIdx.x) * 4;
    if (i >= n) return;
    float4 v = *(const float4*)(in + i);
    v.x *= scale; v.y *= scale; v.z *= scale; v.w *= scale;
    bf16 h0 = __float2bfloat16(v.x), h1 = __float2bfloat16(v.y);
    bf16 h2 = __float2bfloat16(v.z), h3 = __float2bfloat16(v.w);
    bf16 l0 = __float2bfloat16(v.x - __bfloat162float(h0));
    bf16 l1 = __float2bfloat16(v.y - __bfloat162float(h1));
    bf16 l2 = __float2bfloat16(v.z - __bfloat162float(h2));
    bf16 l3 = __float2bfloat16(v.w - __bfloat162float(h3));
    *(__nv_bfloat162*)(hi + i)     = __halves2bfloat162(h0, h1);
    *(__nv_bfloat162*)(hi + i + 2) = __halves2bfloat162(h2, h3);
    *(__nv_bfloat162*)(lo + i)     = __halves2bfloat162(l0, l1);
    *(__nv_bfloat162*)(lo + i + 2) = __halves2bfloat162(l2, l3);
}

// ---------------------------------------------------------------------------
// V[S,D] fp32 -> V^T[D,S] bf16 hi/lo
// ---------------------------------------------------------------------------
__global__ __launch_bounds__(256)
void transpose_split(const float* __restrict__ V, bf16* __restrict__ hi,
                     bf16* __restrict__ lo)
{
    __shared__ float t[32][33];
    const int tx = threadIdx.x & 31, ty = threadIdx.x >> 5;
    const int s0 = blockIdx.x * 32, d0 = blockIdx.y * 32;
#pragma unroll
    for (int j = 0; j < 4; j++)
        t[ty + 8 * j][tx] = V[(size_t)(s0 + ty + 8 * j) * DMODEL + d0 + tx];
    __syncthreads();
#pragma unroll
    for (int j = 0; j < 4; j++) {
        int d = d0 + ty + 8 * j, s = s0 + tx;
        float v = t[tx][ty + 8 * j];
        bf16 h = __float2bfloat16(v);
        hi[(size_t)d * S_LEN + s] = h;
        lo[(size_t)d * S_LEN + s] = __float2bfloat16(v - __bfloat162float(h));
    }
}

// ---------------------------------------------------------------------------
// Row softmax over 4096 + normalize + bf16 hi/lo split WRITTEN IN PLACE over
// the fp32 score row: row bf16 units [0,4096) = Phi, [4096,8192) = Plo.
// Safe: all reads complete (registers) before the reduction barriers; all
// writes happen after.
// ---------------------------------------------------------------------------
__global__ __launch_bounds__(256)
void softmax_split_inplace(float* __restrict__ S)
{
    __shared__ float red[8];
    const int tid = threadIdx.x, lid = tid & 31, wid = tid >> 5;
    const size_t row = blockIdx.x;
    float* p = S + row * S_LEN;
    float4 v[4];
#pragma unroll
    for (int j = 0; j < 4; j++)
        v[j] = *(const float4*)(p + (size_t)(tid + 256 * j) * 4);
    float mx = -1e30f;
#pragma unroll
    for (int j = 0; j < 4; j++)
        mx = fmaxf(mx, fmaxf(fmaxf(v[j].x, v[j].y), fmaxf(v[j].z, v[j].w)));
#pragma unroll
    for (int o = 16; o; o >>= 1) mx = fmaxf(mx, __shfl_xor_sync(~0u, mx, o));
    if (lid == 0) red[wid] = mx;
    __syncthreads();
    mx = fmaxf(fmaxf(fmaxf(red[0], red[1]), fmaxf(red[2], red[3])),
               fmaxf(fmaxf(red[4], red[5]), fmaxf(red[6], red[7])));
    float sum = 0.f;
#pragma unroll
    for (int j = 0; j < 4; j++) {
        v[j].x = __expf(v[j].x - mx); v[j].y = __expf(v[j].y - mx);
        v[j].z = __expf(v[j].z - mx); v[j].w = __expf(v[j].w - mx);
        sum += v[j].x + v[j].y + v[j].z + v[j].w;
    }
#pragma unroll
    for (int o = 16; o; o >>= 1) sum += __shfl_xor_sync(~0u, sum, o);
    __syncthreads();
    if (lid == 0) red[wid] = sum;
    __syncthreads();
    sum = red[0] + red[1] + red[2] + red[3] + red[4] + red[5] + red[6] + red[7];
    const float inv = 1.f / sum;

    bf16* hi = (bf16*)p;            // in-place: first 8KB of the row
    bf16* lo = hi + S_LEN;          // second 8KB of the row
#pragma unroll
    for (int j = 0; j < 4; j++) {
        size_t o = (size_t)(tid + 256 * j) * 4;
        float e0 = v[j].x * inv, e1 = v[j].y * inv, e2 = v[j].z * inv, e3 = v[j].w * inv;
        bf16 h0 = __float2bfloat16(e0), h1 = __float2bfloat16(e1);
        bf16 h2 = __float2bfloat16(e2), h3 = __float2bfloat16(e3);
        *(__nv_bfloat162*)(hi + o)     = __halves2bfloat162(h0, h1);
        *(__nv_bfloat162*)(hi + o + 2) = __halves2bfloat162(h2, h3);
        *(__nv_bfloat162*)(lo + o) =
            __halves2bfloat162(__float2bfloat16(e0 - __bfloat162float(h0)),
                               __float2bfloat16(e1 - __bfloat162float(h1)));
        *(__nv_bfloat162*)(lo + o + 2) =
            __halves2bfloat162(__float2bfloat16(e2 - __bfloat162float(h2)),
                               __float2bfloat16(e3 - __bfloat162float(h3)));
    }
}

// ---------------------------------------------------------------------------
extern "C" void kernel_launch(void* const* d_in, const int* in_sizes, int n_in,
                              void* d_out, int out_size)
{
    (void)in_sizes; (void)n_in; (void)out_size;
    const float* x  = (const float*)d_in[0];
    const float* Wq = (const float*)d_in[1];
    const float* bq = (const float*)d_in[2];
    const float* Wk = (const float*)d_in[3];
    const float* bk = (const float*)d_in[4];
    const float* Wv = (const float*)d_in[5];
    const float* bv = (const float*)d_in[6];
    const float* Wo = (const float*)d_in[7];
    const float* bo = (const float*)d_in[8];
    float* out = (float*)d_out;

    float *Qf, *Kf, *Vf, *Cf, *Sf;
    bf16 *xh, *xl, *wqh, *wql, *wkh, *wkl, *wvh, *wvl, *woh, *wol;
    bf16 *qh, *ql, *kh, *kl, *vth, *vtl, *ch, *cl;
    cudaGetSymbolAddress((void**)&Qf, g_Q);
    cudaGetSymbolAddress((void**)&Kf, g_K);
    cudaGetSymbolAddress((void**)&Vf, g_V);
    cudaGetSymbolAddress((void**)&Cf, g_ctx);
    cudaGetSymbolAddress((void**)&Sf, g_S);
    cudaGetSymbolAddress((void**)&xh, g_xh);   cudaGetSymbolAddress((void**)&xl, g_xl);
    cudaGetSymbolAddress((void**)&wqh, g_wqh); cudaGetSymbolAddress((void**)&wql, g_wql);
    cudaGetSymbolAddress((void**)&wkh, g_wkh); cudaGetSymbolAddress((void**)&wkl, g_wkl);
    cudaGetSymbolAddress((void**)&wvh, g_wvh); cudaGetSymbolAddress((void**)&wvl, g_wvl);
    cudaGetSymbolAddress((void**)&woh, g_woh); cudaGetSymbolAddress((void**)&wol, g_wol);
    cudaGetSymbolAddress((void**)&qh, g_qh);   cudaGetSymbolAddress((void**)&ql, g_ql);
    cudaGetSymbolAddress((void**)&kh, g_kh);   cudaGetSymbolAddress((void**)&kl, g_kl);
    cudaGetSymbolAddress((void**)&vth, g_vth); cudaGetSymbolAddress((void**)&vtl, g_vtl);
    cudaGetSymbolAddress((void**)&ch, g_ch);   cudaGetSymbolAddress((void**)&cl, g_cl);

    cudaFuncSetAttribute(gemm_bf16x3, cudaFuncAttributeMaxDynamicSharedMemorySize,
                         GEMM_SMEM);

    const float qscale = 0.08838834764831845f;   // 1/sqrt(128)

    split_kernel<<<SD / 1024, 256>>>(x,  xh,  xl,  1.f, SD);
    split_kernel<<<DD / 1024, 256>>>(Wq, wqh, wql, 1.f, DD);
    split_kernel<<<DD / 1024, 256>>>(Wk, wkh, wkl, 1.f, DD);
    split_kernel<<<DD / 1024, 256>>>(Wv, wvh, wvl, 1.f, DD);
    split_kernel<<<DD / 1024, 256>>>(Wo, woh, wol, 1.f, DD);

    dim3 gProj(DMODEL / BN, S_LEN / BM, 1);     // (16, 32)
    gemm_bf16x3<<<gProj, 256, GEMM_SMEM>>>(xh, xl, wqh, wql, bq, Qf,
                                           DMODEL, DMODEL, DMODEL, DMODEL, 0, 0, 0);
    gemm_bf16x3<<<gProj, 256, GEMM_SMEM>>>(xh, xl, wkh, wkl, bk, Kf,
                                           DMODEL, DMODEL, DMODEL, DMODEL, 0, 0, 0);
    gemm_bf16x3<<<gProj, 256, GEMM_SMEM>>>(xh, xl, wvh, wvl, bv, Vf,
                                           DMODEL, DMODEL, DMODEL, DMODEL, 0, 0, 0);

    split_kernel<<<SD / 1024, 256>>>(Qf, qh, ql, qscale, SD);
    split_kernel<<<SD / 1024, 256>>>(Kf, kh, kl, 1.f, SD);
    transpose_split<<<dim3(S_LEN / 32, DMODEL / 32), 256>>>(Vf, vth, vtl);

    // scores: per head S_h[4096,4096] = Q_h K_h^T (scale folded into Q)
    dim3 gSc(S_LEN / BN, S_LEN / BM, NHEADS);   // (32, 32, 16)
    gemm_bf16x3<<<gSc, 256, GEMM_SMEM>>>(qh, ql, kh, kl, nullptr, Sf,
                                         HDIM, DMODEL, DMODEL, S_LEN,
                                         (size_t)HDIM, (size_t)HDIM, SSQ);

    // softmax + bf16 hi/lo split, in place over g_S
    softmax_split_inplace<<<NHEADS * S_LEN, 256>>>(Sf);

    // PV: per head ctx[:, h*128:+128] = P_h[4096,4096] * V_h  (B = V^T slice)
    // P rows in g_S: hi at row*8192, lo at row*8192+4096 (bf16 units)
    bf16* Pb = (bf16*)Sf;
    dim3 gPV(HDIM / BN, S_LEN / BM, NHEADS);    // (1, 32, 16)
    gemm_bf16x3<<<gPV, 256, GEMM_SMEM>>>(Pb, Pb + S_LEN, vth, vtl, nullptr, Cf,
                                         S_LEN, 2 * S_LEN, S_LEN, DMODEL,
                                         SSQ * 2, (size_t)HDIM * S_LEN, (size_t)HDIM);

    split_kernel<<<SD / 1024, 256>>>(Cf, ch, cl, 1.f, SD);
    gemm_bf16x3<<<gProj, 256, GEMM_SMEM>>>(ch, cl, woh, wol, bo, out,
                                           DMODEL, DMODEL, DMODEL, DMODEL, 0, 0, 0);
}

// round 10
// speedup vs baseline: 2.7283x; 1.2802x over previous
#include <cuda_runtime.h>
#include <cuda_bf16.h>
#include <cstdint>
#include <cstddef>

typedef __nv_bfloat16 bf16;

#define S_LEN  4096
#define DMODEL 2048
#define NHEADS 16
#define HDIM   128

constexpr size_t SD  = (size_t)S_LEN * DMODEL;     // 8,388,608
constexpr size_t DD  = (size_t)DMODEL * DMODEL;    // 4,194,304

// ---------------- static device scratch (no runtime alloc allowed) ----------
__device__ float g_Q[SD];
__device__ float g_K[SD];
__device__ float g_V[SD];
__device__ float g_ctx[SD];
__device__ bf16  g_xh[SD],  g_xl[SD];
__device__ bf16  g_wqh[DD], g_wql[DD], g_wkh[DD], g_wkl[DD];
__device__ bf16  g_wvh[DD], g_wvl[DD], g_woh[DD], g_wol[DD];
__device__ bf16  g_qh[SD],  g_ql[SD];      // Q pre-scaled by 1/sqrt(Hd)
__device__ bf16  g_kh[SD],  g_kl[SD];
__device__ bf16  g_vth[SD], g_vtl[SD];     // V^T  [DMODEL][S_LEN]
__device__ bf16  g_ch[SD],  g_cl[SD];

// ---------------- baseline-PTX helpers (sm_80+, no 'a' features) ------------
__device__ __forceinline__ void cpasync16(uint32_t dst, const void* src) {
    asm volatile("cp.async.cg.shared.global [%0], [%1], 16;" :: "r"(dst), "l"(src));
}
__device__ __forceinline__ void cp_commit() {
    asm volatile("cp.async.commit_group;" ::: "memory");
}
// m16n8k16 row.col bf16 -> fp32 accumulate
__device__ __forceinline__ void mma16816(float* d, const uint32_t* a, const uint32_t* b) {
    asm volatile(
        "mma.sync.aligned.m16n8k16.row.col.f32.bf16.bf16.f32 "
        "{%0,%1,%2,%3}, {%4,%5,%6,%7}, {%8,%9}, {%0,%1,%2,%3};"
        : "+f"(d[0]), "+f"(d[1]), "+f"(d[2]), "+f"(d[3])
        : "r"(a[0]), "r"(a[1]), "r"(a[2]), "r"(a[3]), "r"(b[0]), "r"(b[1]));
}
__device__ __forceinline__ void ldm4(uint32_t* r, uint32_t addr) {
    asm volatile("ldmatrix.sync.aligned.m8n8.x4.shared.b16 {%0,%1,%2,%3}, [%4];"
                 : "=r"(r[0]), "=r"(r[1]), "=r"(r[2]), "=r"(r[3]) : "r"(addr));
}
// pack 2 floats -> bf16x2 hi word, and residual lo word
__device__ __forceinline__ void pack_hl(float x, float y, uint32_t& hi, uint32_t& lo) {
    bf16 hx = __float2bfloat16(x), hy = __float2bfloat16(y);
    __nv_bfloat162 h2 = __halves2bfloat162(hx, hy);
    __nv_bfloat162 l2 = __halves2bfloat162(
        __float2bfloat16(x - __bfloat162float(hx)),
        __float2bfloat16(y - __bfloat162float(hy)));
    hi = *(uint32_t*)&h2;
    lo = *(uint32_t*)&l2;
}

// ---------------------------------------------------------------------------
// Generic bf16x3 GEMM (unchanged from R8 — passing): C = A B^T (+bias)
// ---------------------------------------------------------------------------
#define BM 128
#define BN 128
#define BK 32
#define ROWE   40
#define SUB_B  (128 * ROWE * 2)
#define BUF_B  (4 * SUB_B)
#define GEMM_SMEM (2 * BUF_B)

__global__ __launch_bounds__(256, 1)
void gemm_bf16x3(const bf16* __restrict__ Ahi, const bf16* __restrict__ Alo,
                 const bf16* __restrict__ Bhi, const bf16* __restrict__ Blo,
                 const float* __restrict__ bias, float* __restrict__ C,
                 int K, int lda, int ldb, int ldc)
{
    extern __shared__ char smc[];
    const int tid = threadIdx.x;
    const int wid = tid >> 5, l = tid & 31;
    const int gr = l >> 2, kc = (l & 3) * 2;
    const int warp_m = wid & 3, warp_n = wid >> 2;
    const int n0 = blockIdx.x * BN, m0 = blockIdx.y * BM;

    float acc[2][8][4];
#pragma unroll
    for (int mt = 0; mt < 2; mt++)
#pragma unroll
        for (int nt = 0; nt < 8; nt++)
#pragma unroll
            for (int i = 0; i < 4; i++) acc[mt][nt][i] = 0.f;

    uint32_t smb = (uint32_t)__cvta_generic_to_shared(smc);
    auto load_sub = [&](uint32_t dstbase, const bf16* src, int row0, int ld, int k0) {
#pragma unroll
        for (int i = 0; i < 2; i++) {
            int c = tid + 256 * i;
            int row = c >> 2, col = (c & 3) * 8;
            cpasync16(dstbase + row * (ROWE * 2) + col * 2,
                      src + (size_t)(row0 + row) * ld + k0 + col);
        }
    };
    auto load_tile = [&](int t, int b) {
        uint32_t base = smb + b * BUF_B;
        int k0 = t * BK;
        load_sub(base,             Ahi, m0, lda, k0);
        load_sub(base + SUB_B,     Alo, m0, lda, k0);
        load_sub(base + 2 * SUB_B, Bhi, n0, ldb, k0);
        load_sub(base + 3 * SUB_B, Blo, n0, ldb, k0);
        cp_commit();
    };

    const int T = K / BK;
    load_tile(0, 0);
    for (int t = 0; t < T; t++) {
        const int b = t & 1;
        asm volatile("cp.async.wait_group 0;" ::: "memory");
        __syncthreads();
        if (t + 1 < T) load_tile(t + 1, 1 ^ b);

        const char* base = smc + b * BUF_B;
        const bf16* sAh = (const bf16*)(base);
        const bf16* sAl = (const bf16*)(base + SUB_B);
        const bf16* sBh = (const bf16*)(base + 2 * SUB_B);
        const bf16* sBl = (const bf16*)(base + 3 * SUB_B);

#pragma unroll
        for (int ks = 0; ks < 2; ks++) {
            const int kb = ks * 16 + kc;
            uint32_t ah[2][4], al[2][4];
#pragma unroll
            for (int mt = 0; mt < 2; mt++) {
                const int r = warp_m * 32 + mt * 16 + gr;
                ah[mt][0] = *(const uint32_t*)&sAh[(r)     * ROWE + kb];
                ah[mt][1] = *(const uint32_t*)&sAh[(r + 8) * ROWE + kb];
                ah[mt][2] = *(const uint32_t*)&sAh[(r)     * ROWE + kb + 8];
                ah[mt][3] = *(const uint32_t*)&sAh[(r + 8) * ROWE + kb + 8];
                al[mt][0] = *(const uint32_t*)&sAl[(r)     * ROWE + kb];
                al[mt][1] = *(const uint32_t*)&sAl[(r + 8) * ROWE + kb];
                al[mt][2] = *(const uint32_t*)&sAl[(r)     * ROWE + kb + 8];
                al[mt][3] = *(const uint32_t*)&sAl[(r + 8) * ROWE + kb + 8];
            }
            uint32_t bh[8][2], bl[8][2];
#pragma unroll
            for (int nt = 0; nt < 8; nt++) {
                const int n = warp_n * 64 + nt * 8 + gr;
                bh[nt][0] = *(const uint32_t*)&sBh[n * ROWE + kb];
                bh[nt][1] = *(const uint32_t*)&sBh[n * ROWE + kb + 8];
                bl[nt][0] = *(const uint32_t*)&sBl[n * ROWE + kb];
                bl[nt][1] = *(const uint32_t*)&sBl[n * ROWE + kb + 8];
            }
#pragma unroll
            for (int mt = 0; mt < 2; mt++)
#pragma unroll
                for (int nt = 0; nt < 8; nt++) {
                    mma16816(acc[mt][nt], ah[mt], bh[nt]);
                    mma16816(acc[mt][nt], ah[mt], bl[nt]);
                    mma16816(acc[mt][nt], al[mt], bh[nt]);
                }
        }
        __syncthreads();
    }

#pragma unroll
    for (int nt = 0; nt < 8; nt++) {
        const int c = n0 + warp_n * 64 + nt * 8 + kc;
        float2 bv = make_float2(0.f, 0.f);
        if (bias) bv = *(const float2*)&bias[c];
#pragma unroll
        for (int mt = 0; mt < 2; mt++) {
            const int r = m0 + warp_m * 32 + mt * 16 + gr;
            *(float2*)&C[(size_t)r * ldc + c] =
                make_float2(acc[mt][nt][0] + bv.x, acc[mt][nt][1] + bv.y);
            *(float2*)&C[(size_t)(r + 8) * ldc + c] =
                make_float2(acc[mt][nt][2] + bv.x, acc[mt][nt][3] + bv.y);
        }
    }
}

// ---------------------------------------------------------------------------
// Fused flash attention, bf16x3 on mma.sync.
// Grid (32 q-blocks, 16 heads), 256 threads = 8 warps; warp w owns q rows
// [w*16, w*16+16). K-loop tiles of 64 keys, double-buffered cp.async.
// Q tile (128x128 hi/lo) resident in smem. P stays in registers (FA2 layout
// trick: m16n8 C-accum == m16n8k16 A-frag after bf16 packing).
// ---------------------------------------------------------------------------
#define QSTR 136                        // bf16 units (272 B)
#define KSTR 136
#define VSTR 72                         // 144 B
#define OFF_QL (128 * QSTR * 2)         // 34816
#define OFF_BUF (2 * OFF_QL)            // 69632
#define KH_B (64 * KSTR * 2)            // 17408
#define VT_B (128 * VSTR * 2)           // 18432
#define OFF_VT (2 * KH_B)               // within buffer: Kh|Kl|VTh|VTl
#define FBUF_B (2 * KH_B + 2 * VT_B)    // 71680
#define ATT_SMEM (OFF_BUF + 2 * FBUF_B) // 212992
#define NIT (S_LEN / 64)

__global__ __launch_bounds__(256, 1)
void flash_attn(const bf16* __restrict__ Qh, const bf16* __restrict__ Ql,
                const bf16* __restrict__ Kh, const bf16* __restrict__ Kl,
                const bf16* __restrict__ VTh, const bf16* __restrict__ VTl,
                float* __restrict__ ctx)
{
    extern __shared__ char smem[];
    const uint32_t smb = (uint32_t)__cvta_generic_to_shared(smem);
    const int tid = threadIdx.x;
    const int warp = tid >> 5, L = tid & 31;
    const int qb = blockIdx.x, h = blockIdx.y;

    // ---- loaders (cp.async 16B) ----
    const size_t qrow0 = (size_t)qb * 128;
    auto loadQ = [&]() {
        // Q tile: 128 rows x 16 chunks = 2048 chunks per half -> i < 8  (R9 bug: was 4)
#pragma unroll
        for (int i = 0; i < 8; i++) {
            int c = tid + 256 * i;
            int row = c >> 4, col = c & 15;
            cpasync16(smb + row * (QSTR * 2) + col * 16,
                      Qh + (qrow0 + row) * DMODEL + h * HDIM + col * 8);
        }
#pragma unroll
        for (int i = 0; i < 8; i++) {
            int c = tid + 256 * i;
            int row = c >> 4, col = c & 15;
            cpasync16(smb + OFF_QL + row * (QSTR * 2) + col * 16,
                      Ql + (qrow0 + row) * DMODEL + h * HDIM + col * 8);
        }
    };
    auto loadKV = [&](int it, int b) {
        const uint32_t bb = smb + OFF_BUF + b * FBUF_B;
        const size_t krow0 = (size_t)it * 64;
#pragma unroll
        for (int i = 0; i < 4; i++) {           // Kh: 64 rows x 16 chunks
            int c = tid + 256 * i;
            int row = c >> 4, col = c & 15;
            cpasync16(bb + row * (KSTR * 2) + col * 16,
                      Kh + (krow0 + row) * DMODEL + h * HDIM + col * 8);
        }
#pragma unroll
        for (int i = 0; i < 4; i++) {
            int c = tid + 256 * i;
            int row = c >> 4, col = c & 15;
            cpasync16(bb + KH_B + row * (KSTR * 2) + col * 16,
                      Kl + (krow0 + row) * DMODEL + h * HDIM + col * 8);
        }
#pragma unroll
        for (int i = 0; i < 4; i++) {           // VTh: 128 d-rows x 8 chunks
            int c = tid + 256 * i;
            int row = c >> 3, col = c & 7;
            cpasync16(bb + OFF_VT + row * (VSTR * 2) + col * 16,
                      VTh + (size_t)(h * HDIM + row) * S_LEN + krow0 + col * 8);
        }
#pragma unroll
        for (int i = 0; i < 4; i++) {
            int c = tid + 256 * i;
            int row = c >> 3, col = c & 7;
            cpasync16(bb + OFF_VT + VT_B + row * (VSTR * 2) + col * 16,
                      VTl + (size_t)(h * HDIM + row) * S_LEN + krow0 + col * 8);
        }
        cp_commit();
    };

    // ---- per-lane ldmatrix base offsets ----
    const uint32_t a_off = (warp * 16 + (L & 15)) * (QSTR * 2) + (L >> 4) * 16;
    const uint32_t brow = (L & 7) + ((L >> 4) & 1) * 8;
    const uint32_t bcol16 = ((L >> 3) & 1) * 16;

    float O[16][4];
#pragma unroll
    for (int dt = 0; dt < 16; dt++)
#pragma unroll
        for (int i = 0; i < 4; i++) O[dt][i] = 0.f;
    float m0 = -1e30f, m1 = -1e30f, l0 = 0.f, l1 = 0.f;

    loadQ();
    loadKV(0, 0);

    for (int it = 0; it < NIT; it++) {
        const int b = it & 1;
        if (it + 1 < NIT) loadKV(it + 1, 1 ^ b);
        if (it + 1 < NIT)
            asm volatile("cp.async.wait_group 1;" ::: "memory");
        else
            asm volatile("cp.async.wait_group 0;" ::: "memory");
        __syncthreads();

        const uint32_t bb = smb + OFF_BUF + b * FBUF_B;
        const uint32_t kaddr = bb + brow * (KSTR * 2) + bcol16;
        const uint32_t vaddr = bb + OFF_VT + brow * (VSTR * 2) + bcol16;

        // ---- S = Q K^T (bf16x3) ----
        float S[8][4];
#pragma unroll
        for (int nt = 0; nt < 8; nt++)
#pragma unroll
            for (int i = 0; i < 4; i++) S[nt][i] = 0.f;

#pragma unroll
        for (int ks = 0; ks < 8; ks++) {
            uint32_t ah[4], al[4];
            ldm4(ah, smb + a_off + ks * 32);
            ldm4(al, smb + OFF_QL + a_off + ks * 32);
#pragma unroll
            for (int ntp = 0; ntp < 4; ntp++) {
                uint32_t bh[4], bl[4];
                ldm4(bh, kaddr + ntp * (16 * KSTR * 2) + ks * 32);
                ldm4(bl, kaddr + KH_B + ntp * (16 * KSTR * 2) + ks * 32);
                mma16816(S[2 * ntp],     ah, bh);
                mma16816(S[2 * ntp + 1], ah, bh + 2);
                mma16816(S[2 * ntp],     ah, bl);
                mma16816(S[2 * ntp + 1], ah, bl + 2);
                mma16816(S[2 * ntp],     al, bh);
                mma16816(S[2 * ntp + 1], al, bh + 2);
            }
        }

        // ---- online softmax (rows r = L>>2 and r+8) ----
        float mx0 = -1e30f, mx1 = -1e30f;
#pragma unroll
        for (int nt = 0; nt < 8; nt++) {
            mx0 = fmaxf(mx0, fmaxf(S[nt][0], S[nt][1]));
            mx1 = fmaxf(mx1, fmaxf(S[nt][2], S[nt][3]));
        }
        mx0 = fmaxf(mx0, __shfl_xor_sync(~0u, mx0, 1));
        mx0 = fmaxf(mx0, __shfl_xor_sync(~0u, mx0, 2));
        mx1 = fmaxf(mx1, __shfl_xor_sync(~0u, mx1, 1));
        mx1 = fmaxf(mx1, __shfl_xor_sync(~0u, mx1, 2));
        const float m0n = fmaxf(m0, mx0), m1n = fmaxf(m1, mx1);
        const float al0 = __expf(m0 - m0n), al1 = __expf(m1 - m1n);
        m0 = m0n; m1 = m1n;
        float rs0 = 0.f, rs1 = 0.f;
#pragma unroll
        for (int nt = 0; nt < 8; nt++) {
            S[nt][0] = __expf(S[nt][0] - m0n); S[nt][1] = __expf(S[nt][1] - m0n);
            S[nt][2] = __expf(S[nt][2] - m1n); S[nt][3] = __expf(S[nt][3] - m1n);
            rs0 += S[nt][0] + S[nt][1];
            rs1 += S[nt][2] + S[nt][3];
        }
        rs0 += __shfl_xor_sync(~0u, rs0, 1); rs0 += __shfl_xor_sync(~0u, rs0, 2);
        rs1 += __shfl_xor_sync(~0u, rs1, 1); rs1 += __shfl_xor_sync(~0u, rs1, 2);
        l0 = l0 * al0 + rs0;
        l1 = l1 * al1 + rs1;
#pragma unroll
        for (int dt = 0; dt < 16; dt++) {
            O[dt][0] *= al0; O[dt][1] *= al0;
            O[dt][2] *= al1; O[dt][3] *= al1;
        }

        // ---- O += P V (P from registers via FA2 layout; bf16x3) ----
#pragma unroll
        for (int ks = 0; ks < 4; ks++) {
            uint32_t ph[4], pl[4];
            pack_hl(S[2 * ks][0],     S[2 * ks][1],     ph[0], pl[0]);
            pack_hl(S[2 * ks][2],     S[2 * ks][3],     ph[1], pl[1]);
            pack_hl(S[2 * ks + 1][0], S[2 * ks + 1][1], ph[2], pl[2]);
            pack_hl(S[2 * ks + 1][2], S[2 * ks + 1][3], ph[3], pl[3]);
#pragma unroll
            for (int dtp = 0; dtp < 8; dtp++) {
                uint32_t bh[4], bl[4];
                ldm4(bh, vaddr + dtp * (16 * VSTR * 2) + ks * 32);
                ldm4(bl, vaddr + VT_B + dtp * (16 * VSTR * 2) + ks * 32);
                mma16816(O[2 * dtp],     ph, bh);
                mma16816(O[2 * dtp + 1], ph, bh + 2);
                mma16816(O[2 * dtp],     ph, bl);
                mma16816(O[2 * dtp + 1], ph, bl + 2);
                mma16816(O[2 * dtp],     pl, bh);
                mma16816(O[2 * dtp + 1], pl, bh + 2);
            }
        }
        __syncthreads();   // protect buffer b before next-iter overwrite
    }

    // ---- finalize ----
    const float inv0 = 1.f / l0, inv1 = 1.f / l1;
    const size_t q = qrow0 + warp * 16 + (L >> 2);
    float* o0 = ctx + q * DMODEL + h * HDIM + (L & 3) * 2;
#pragma unroll
    for (int dt = 0; dt < 16; dt++) {
        *(float2*)(o0 + dt * 8) =
            make_float2(O[dt][0] * inv0, O[dt][1] * inv0);
        *(float2*)(o0 + (size_t)8 * DMODEL + dt * 8) =
            make_float2(O[dt][2] * inv1, O[dt][3] * inv1);
    }
}

// ---------------------------------------------------------------------------
__global__ __launch_bounds__(256)
void split_kernel(const float* __restrict__ in, bf16* __restrict__ hi,
                  bf16* __restrict__ lo, float scale, size_t n)
{
    size_t i = ((size_t)blockIdx.x * 256 + threadIdx.x) * 4;
    if (i >= n) return;
    float4 v = *(const float4*)(in + i);
    v.x *= scale; v.y *= scale; v.z *= scale; v.w *= scale;
    bf16 h0 = __float2bfloat16(v.x), h1 = __float2bfloat16(v.y);
    bf16 h2 = __float2bfloat16(v.z), h3 = __float2bfloat16(v.w);
    *(__nv_bfloat162*)(hi + i)     = __halves2bfloat162(h0, h1);
    *(__nv_bfloat162*)(hi + i + 2) = __halves2bfloat162(h2, h3);
    *(__nv_bfloat162*)(lo + i) = __halves2bfloat162(
        __float2bfloat16(v.x - __bfloat162float(h0)),
        __float2bfloat16(v.y - __bfloat162float(h1)));
    *(__nv_bfloat162*)(lo + i + 2) = __halves2bfloat162(
        __float2bfloat16(v.z - __bfloat162float(h2)),
        __float2bfloat16(v.w - __bfloat162float(h3)));
}

__global__ __launch_bounds__(256)
void transpose_split(const float* __restrict__ V, bf16* __restrict__ hi,
                     bf16* __restrict__ lo)
{
    __shared__ float t[32][33];
    const int tx = threadIdx.x & 31, ty = threadIdx.x >> 5;
    const int s0 = blockIdx.x * 32, d0 = blockIdx.y * 32;
#pragma unroll
    for (int j = 0; j < 4; j++)
        t[ty + 8 * j][tx] = V[(size_t)(s0 + ty + 8 * j) * DMODEL + d0 + tx];
    __syncthreads();
#pragma unroll
    for (int j = 0; j < 4; j++) {
        int d = d0 + ty + 8 * j, s = s0 + tx;
        float v = t[tx][ty + 8 * j];
        bf16 hv = __float2bfloat16(v);
        hi[(size_t)d * S_LEN + s] = hv;
        lo[(size_t)d * S_LEN + s] = __float2bfloat16(v - __bfloat162float(hv));
    }
}

// ---------------------------------------------------------------------------
extern "C" void kernel_launch(void* const* d_in, const int* in_sizes, int n_in,
                              void* d_out, int out_size)
{
    (void)in_sizes; (void)n_in; (void)out_size;
    const float* x  = (const float*)d_in[0];
    const float* Wq = (const float*)d_in[1];
    const float* bq = (const float*)d_in[2];
    const float* Wk = (const float*)d_in[3];
    const float* bk = (const float*)d_in[4];
    const float* Wv = (const float*)d_in[5];
    const float* bv = (const float*)d_in[6];
    const float* Wo = (const float*)d_in[7];
    const float* bo = (const float*)d_in[8];
    float* out = (float*)d_out;

    float *Qf, *Kf, *Vf, *Cf;
    bf16 *xh, *xl, *wqh, *wql, *wkh, *wkl, *wvh, *wvl, *woh, *wol;
    bf16 *qh, *ql, *kh, *kl, *vth, *vtl, *ch, *cl;
    cudaGetSymbolAddress((void**)&Qf, g_Q);
    cudaGetSymbolAddress((void**)&Kf, g_K);
    cudaGetSymbolAddress((void**)&Vf, g_V);
    cudaGetSymbolAddress((void**)&Cf, g_ctx);
    cudaGetSymbolAddress((void**)&xh, g_xh);   cudaGetSymbolAddress((void**)&xl, g_xl);
    cudaGetSymbolAddress((void**)&wqh, g_wqh); cudaGetSymbolAddress((void**)&wql, g_wql);
    cudaGetSymbolAddress((void**)&wkh, g_wkh); cudaGetSymbolAddress((void**)&wkl, g_wkl);
    cudaGetSymbolAddress((void**)&wvh, g_wvh); cudaGetSymbolAddress((void**)&wvl, g_wvl);
    cudaGetSymbolAddress((void**)&woh, g_woh); cudaGetSymbolAddress((void**)&wol, g_wol);
    cudaGetSymbolAddress((void**)&qh, g_qh);   cudaGetSymbolAddress((void**)&ql, g_ql);
    cudaGetSymbolAddress((void**)&kh, g_kh);   cudaGetSymbolAddress((void**)&kl, g_kl);
    cudaGetSymbolAddress((void**)&vth, g_vth); cudaGetSymbolAddress((void**)&vtl, g_vtl);
    cudaGetSymbolAddress((void**)&ch, g_ch);   cudaGetSymbolAddress((void**)&cl, g_cl);

    cudaFuncSetAttribute(gemm_bf16x3, cudaFuncAttributeMaxDynamicSharedMemorySize,
                         GEMM_SMEM);
    cudaFuncSetAttribute(flash_attn, cudaFuncAttributeMaxDynamicSharedMemorySize,
                         ATT_SMEM);

    const float qscale = 0.08838834764831845f;   // 1/sqrt(128)

    split_kernel<<<SD / 1024, 256>>>(x,  xh,  xl,  1.f, SD);
    split_kernel<<<DD / 1024, 256>>>(Wq, wqh, wql, 1.f, DD);
    split_kernel<<<DD / 1024, 256>>>(Wk, wkh, wkl, 1.f, DD);
    split_kernel<<<DD / 1024, 256>>>(Wv, wvh, wvl, 1.f, DD);
    split_kernel<<<DD / 1024, 256>>>(Wo, woh, wol, 1.f, DD);

    dim3 gProj(DMODEL / BN, S_LEN / BM);        // (16, 32)
    gemm_bf16x3<<<gProj, 256, GEMM_SMEM>>>(xh, xl, wqh, wql, bq, Qf,
                                           DMODEL, DMODEL, DMODEL, DMODEL);
    gemm_bf16x3<<<gProj, 256, GEMM_SMEM>>>(xh, xl, wkh, wkl, bk, Kf,
                                           DMODEL, DMODEL, DMODEL, DMODEL);
    gemm_bf16x3<<<gProj, 256, GEMM_SMEM>>>(xh, xl, wvh, wvl, bv, Vf,
                                           DMODEL, DMODEL, DMODEL, DMODEL);

    split_kernel<<<SD / 1024, 256>>>(Qf, qh, ql, qscale, SD);
    split_kernel<<<SD / 1024, 256>>>(Kf, kh, kl, 1.f, SD);
    transpose_split<<<dim3(S_LEN / 32, DMODEL / 32), 256>>>(Vf, vth, vtl);

    // fused attention: scores + softmax + PV
    flash_attn<<<dim3(S_LEN / 128, NHEADS), 256, ATT_SMEM>>>(qh, ql, kh, kl,
                                                             vth, vtl, Cf);

    split_kernel<<<SD / 1024, 256>>>(Cf, ch, cl, 1.f, SD);
    gemm_bf16x3<<<gProj, 256, GEMM_SMEM>>>(ch, cl, woh, wol, bo, out,
                                           DMODEL, DMODEL, DMODEL, DMODEL);
}

// round 11
// speedup vs baseline: 2.9502x; 1.0813x over previous
#include <cuda_runtime.h>
#include <cuda_bf16.h>
#include <cstdint>
#include <cstddef>

typedef __nv_bfloat16 bf16;

#define S_LEN  4096
#define DMODEL 2048
#define NHEADS 16
#define HDIM   128

constexpr size_t SD  = (size_t)S_LEN * DMODEL;     // 8,388,608
constexpr size_t DD  = (size_t)DMODEL * DMODEL;    // 4,194,304

// ---------------- static device scratch (no runtime alloc allowed) ----------
__device__ float g_V[SD];
__device__ bf16  g_xh[SD],  g_xl[SD];
__device__ bf16  g_wqh[DD], g_wql[DD], g_wkh[DD], g_wkl[DD];
__device__ bf16  g_wvh[DD], g_wvl[DD], g_woh[DD], g_wol[DD];
__device__ bf16  g_qh[SD],  g_ql[SD];      // Q pre-scaled by 1/sqrt(Hd)
__device__ bf16  g_kh[SD],  g_kl[SD];
__device__ bf16  g_vth[SD], g_vtl[SD];     // V^T  [DMODEL][S_LEN]
__device__ bf16  g_ch[SD],  g_cl[SD];

// ---------------- baseline-PTX helpers (sm_80+, no 'a' features) ------------
__device__ __forceinline__ void cpasync16(uint32_t dst, const void* src) {
    asm volatile("cp.async.cg.shared.global [%0], [%1], 16;" :: "r"(dst), "l"(src));
}
__device__ __forceinline__ void cp_commit() {
    asm volatile("cp.async.commit_group;" ::: "memory");
}
// m16n8k16 row.col bf16 -> fp32 accumulate
__device__ __forceinline__ void mma16816(float* d, const uint32_t* a, const uint32_t* b) {
    asm volatile(
        "mma.sync.aligned.m16n8k16.row.col.f32.bf16.bf16.f32 "
        "{%0,%1,%2,%3}, {%4,%5,%6,%7}, {%8,%9}, {%0,%1,%2,%3};"
        : "+f"(d[0]), "+f"(d[1]), "+f"(d[2]), "+f"(d[3])
        : "r"(a[0]), "r"(a[1]), "r"(a[2]), "r"(a[3]), "r"(b[0]), "r"(b[1]));
}
__device__ __forceinline__ void ldm4(uint32_t* r, uint32_t addr) {
    asm volatile("ldmatrix.sync.aligned.m8n8.x4.shared.b16 {%0,%1,%2,%3}, [%4];"
                 : "=r"(r[0]), "=r"(r[1]), "=r"(r[2]), "=r"(r[3]) : "r"(addr));
}
// pack 2 floats -> bf16x2 hi word, and residual lo word
__device__ __forceinline__ void pack_hl(float x, float y, uint32_t& hi, uint32_t& lo) {
    bf16 hx = __float2bfloat16(x), hy = __float2bfloat16(y);
    __nv_bfloat162 h2 = __halves2bfloat162(hx, hy);
    __nv_bfloat162 l2 = __halves2bfloat162(
        __float2bfloat16(x - __bfloat162float(hx)),
        __float2bfloat16(y - __bfloat162float(hy)));
    hi = *(uint32_t*)&h2;
    lo = *(uint32_t*)&l2;
}

// ---------------------------------------------------------------------------
// Generic bf16x3 GEMM: C = (Ahi+Alo)(Bhi+Blo)^T + bias.
// BK=64 (half the barriers of R8/R10), double-buffered cp.async.
// Epilogue either writes fp32 (Cf32) or a scaled bf16 hi/lo split (Chi/Clo).
// ---------------------------------------------------------------------------
#define BM 128
#define BN 128
#define BK 64
#define ROWE   72                      // 64 + 8 pad (bf16 units); conflict-free
#define SUB_B  (128 * ROWE * 2)        // 18432
#define BUF_B  (4 * SUB_B)             // 73728
#define GEMM_SMEM (2 * BUF_B)          // 147456

__global__ __launch_bounds__(256, 1)
void gemm_bf16x3(const bf16* __restrict__ Ahi, const bf16* __restrict__ Alo,
                 const bf16* __restrict__ Bhi, const bf16* __restrict__ Blo,
                 const float* __restrict__ bias,
                 float* __restrict__ Cf32,
                 bf16* __restrict__ Chi, bf16* __restrict__ Clo, float scale,
                 int K, int lda, int ldb, int ldc)
{
    extern __shared__ char smc[];
    const int tid = threadIdx.x;
    const int wid = tid >> 5, l = tid & 31;
    const int gr = l >> 2, kc = (l & 3) * 2;
    const int warp_m = wid & 3, warp_n = wid >> 2;
    const int n0 = blockIdx.x * BN, m0 = blockIdx.y * BM;

    float acc[2][8][4];
#pragma unroll
    for (int mt = 0; mt < 2; mt++)
#pragma unroll
        for (int nt = 0; nt < 8; nt++)
#pragma unroll
            for (int i = 0; i < 4; i++) acc[mt][nt][i] = 0.f;

    uint32_t smb = (uint32_t)__cvta_generic_to_shared(smc);
    // one subtile = 128 rows x 8 chunks (64 bf16) = 1024 chunks; 256 thr x 4
    auto load_sub = [&](uint32_t dstbase, const bf16* src, int row0, int ld, int k0) {
#pragma unroll
        for (int i = 0; i < 4; i++) {
            int c = tid + 256 * i;
            int row = c >> 3, col = (c & 7) * 8;
            cpasync16(dstbase + row * (ROWE * 2) + col * 2,
                      src + (size_t)(row0 + row) * ld + k0 + col);
        }
    };
    auto load_tile = [&](int t, int b) {
        uint32_t base = smb + b * BUF_B;
        int k0 = t * BK;
        load_sub(base,             Ahi, m0, lda, k0);
        load_sub(base + SUB_B,     Alo, m0, lda, k0);
        load_sub(base + 2 * SUB_B, Bhi, n0, ldb, k0);
        load_sub(base + 3 * SUB_B, Blo, n0, ldb, k0);
        cp_commit();
    };

    const int T = K / BK;
    load_tile(0, 0);
    for (int t = 0; t < T; t++) {
        const int b = t & 1;
        asm volatile("cp.async.wait_group 0;" ::: "memory");
        __syncthreads();
        if (t + 1 < T) load_tile(t + 1, 1 ^ b);

        const char* base = smc + b * BUF_B;
        const bf16* sAh = (const bf16*)(base);
        const bf16* sAl = (const bf16*)(base + SUB_B);
        const bf16* sBh = (const bf16*)(base + 2 * SUB_B);
        const bf16* sBl = (const bf16*)(base + 3 * SUB_B);

#pragma unroll
        for (int ks = 0; ks < 4; ks++) {
            const int kb = ks * 16 + kc;
            uint32_t ah[2][4], al[2][4];
#pragma unroll
            for (int mt = 0; mt < 2; mt++) {
                const int r = warp_m * 32 + mt * 16 + gr;
                ah[mt][0] = *(const uint32_t*)&sAh[(r)     * ROWE + kb];
                ah[mt][1] = *(const uint32_t*)&sAh[(r + 8) * ROWE + kb];
                ah[mt][2] = *(const uint32_t*)&sAh[(r)     * ROWE + kb + 8];
                ah[mt][3] = *(const uint32_t*)&sAh[(r + 8) * ROWE + kb + 8];
                al[mt][0] = *(const uint32_t*)&sAl[(r)     * ROWE + kb];
                al[mt][1] = *(const uint32_t*)&sAl[(r + 8) * ROWE + kb];
                al[mt][2] = *(const uint32_t*)&sAl[(r)     * ROWE + kb + 8];
                al[mt][3] = *(const uint32_t*)&sAl[(r + 8) * ROWE + kb + 8];
            }
            uint32_t bh[8][2], bl[8][2];
#pragma unroll
            for (int nt = 0; nt < 8; nt++) {
                const int n = warp_n * 64 + nt * 8 + gr;
                bh[nt][0] = *(const uint32_t*)&sBh[n * ROWE + kb];
                bh[nt][1] = *(const uint32_t*)&sBh[n * ROWE + kb + 8];
                bl[nt][0] = *(const uint32_t*)&sBl[n * ROWE + kb];
                bl[nt][1] = *(const uint32_t*)&sBl[n * ROWE + kb + 8];
            }
#pragma unroll
            for (int mt = 0; mt < 2; mt++)
#pragma unroll
                for (int nt = 0; nt < 8; nt++) {
                    mma16816(acc[mt][nt], ah[mt], bh[nt]);
                    mma16816(acc[mt][nt], ah[mt], bl[nt]);
                    mma16816(acc[mt][nt], al[mt], bh[nt]);
                }
        }
        __syncthreads();
    }

#pragma unroll
    for (int nt = 0; nt < 8; nt++) {
        const int c = n0 + warp_n * 64 + nt * 8 + kc;
        float2 bv = make_float2(0.f, 0.f);
        if (bias) bv = *(const float2*)&bias[c];
#pragma unroll
        for (int mt = 0; mt < 2; mt++) {
            const int r = m0 + warp_m * 32 + mt * 16 + gr;
            float x0 = acc[mt][nt][0] + bv.x, y0 = acc[mt][nt][1] + bv.y;
            float x1 = acc[mt][nt][2] + bv.x, y1 = acc[mt][nt][3] + bv.y;
            if (Cf32) {
                *(float2*)&Cf32[(size_t)r * ldc + c]       = make_float2(x0, y0);
                *(float2*)&Cf32[(size_t)(r + 8) * ldc + c] = make_float2(x1, y1);
            } else {
                x0 *= scale; y0 *= scale; x1 *= scale; y1 *= scale;
                uint32_t h0, l0, h1, l1;
                pack_hl(x0, y0, h0, l0);
                pack_hl(x1, y1, h1, l1);
                *(uint32_t*)&Chi[(size_t)r * ldc + c]       = h0;
                *(uint32_t*)&Clo[(size_t)r * ldc + c]       = l0;
                *(uint32_t*)&Chi[(size_t)(r + 8) * ldc + c] = h1;
                *(uint32_t*)&Clo[(size_t)(r + 8) * ldc + c] = l1;
            }
        }
    }
}

// ---------------------------------------------------------------------------
// Fused flash attention, bf16x3 on mma.sync (passing R10 core).
// Epilogue now writes the ctx bf16 hi/lo split directly (no fp32 round-trip).
// ---------------------------------------------------------------------------
#define QSTR 136                        // bf16 units (272 B)
#define KSTR 136
#define VSTR 72                         // 144 B
#define OFF_QL (128 * QSTR * 2)         // 34816
#define OFF_BUF (2 * OFF_QL)            // 69632
#define KH_B (64 * KSTR * 2)            // 17408
#define VT_B (128 * VSTR * 2)           // 18432
#define OFF_VT (2 * KH_B)               // within buffer: Kh|Kl|VTh|VTl
#define FBUF_B (2 * KH_B + 2 * VT_B)    // 71680
#define ATT_SMEM (OFF_BUF + 2 * FBUF_B) // 212992
#define NIT (S_LEN / 64)

__global__ __launch_bounds__(256, 1)
void flash_attn(const bf16* __restrict__ Qh, const bf16* __restrict__ Ql,
                const bf16* __restrict__ Kh, const bf16* __restrict__ Kl,
                const bf16* __restrict__ VTh, const bf16* __restrict__ VTl,
                bf16* __restrict__ Ch, bf16* __restrict__ Cl)
{
    extern __shared__ char smem[];
    const uint32_t smb = (uint32_t)__cvta_generic_to_shared(smem);
    const int tid = threadIdx.x;
    const int warp = tid >> 5, L = tid & 31;
    const int qb = blockIdx.x, h = blockIdx.y;

    const size_t qrow0 = (size_t)qb * 128;
    auto loadQ = [&]() {
        // 128 rows x 16 chunks = 2048 chunks per half
#pragma unroll
        for (int i = 0; i < 8; i++) {
            int c = tid + 256 * i;
            int row = c >> 4, col = c & 15;
            cpasync16(smb + row * (QSTR * 2) + col * 16,
                      Qh + (qrow0 + row) * DMODEL + h * HDIM + col * 8);
        }
#pragma unroll
        for (int i = 0; i < 8; i++) {
            int c = tid + 256 * i;
            int row = c >> 4, col = c & 15;
            cpasync16(smb + OFF_QL + row * (QSTR * 2) + col * 16,
                      Ql + (qrow0 + row) * DMODEL + h * HDIM + col * 8);
        }
    };
    auto loadKV = [&](int it, int b) {
        const uint32_t bb = smb + OFF_BUF + b * FBUF_B;
        const size_t krow0 = (size_t)it * 64;
#pragma unroll
        for (int i = 0; i < 4; i++) {           // Kh: 64 rows x 16 chunks
            int c = tid + 256 * i;
            int row = c >> 4, col = c & 15;
            cpasync16(bb + row * (KSTR * 2) + col * 16,
                      Kh + (krow0 + row) * DMODEL + h * HDIM + col * 8);
        }
#pragma unroll
        for (int i = 0; i < 4; i++) {
            int c = tid + 256 * i;
            int row = c >> 4, col = c & 15;
            cpasync16(bb + KH_B + row * (KSTR * 2) + col * 16,
                      Kl + (krow0 + row) * DMODEL + h * HDIM + col * 8);
        }
#pragma unroll
        for (int i = 0; i < 4; i++) {           // VTh: 128 d-rows x 8 chunks
            int c = tid + 256 * i;
            int row = c >> 3, col = c & 7;
            cpasync16(bb + OFF_VT + row * (VSTR * 2) + col * 16,
                      VTh + (size_t)(h * HDIM + row) * S_LEN + krow0 + col * 8);
        }
#pragma unroll
        for (int i = 0; i < 4; i++) {
            int c = tid + 256 * i;
            int row = c >> 3, col = c & 7;
            cpasync16(bb + OFF_VT + VT_B + row * (VSTR * 2) + col * 16,
                      VTl + (size_t)(h * HDIM + row) * S_LEN + krow0 + col * 8);
        }
        cp_commit();
    };

    const uint32_t a_off = (warp * 16 + (L & 15)) * (QSTR * 2) + (L >> 4) * 16;
    const uint32_t brow = (L & 7) + ((L >> 4) & 1) * 8;
    const uint32_t bcol16 = ((L >> 3) & 1) * 16;

    float O[16][4];
#pragma unroll
    for (int dt = 0; dt < 16; dt++)
#pragma unroll
        for (int i = 0; i < 4; i++) O[dt][i] = 0.f;
    float m0 = -1e30f, m1 = -1e30f, l0 = 0.f, l1 = 0.f;

    loadQ();
    loadKV(0, 0);

    for (int it = 0; it < NIT; it++) {
        const int b = it & 1;
        if (it + 1 < NIT) loadKV(it + 1, 1 ^ b);
        if (it + 1 < NIT)
            asm volatile("cp.async.wait_group 1;" ::: "memory");
        else
            asm volatile("cp.async.wait_group 0;" ::: "memory");
        __syncthreads();

        const uint32_t bb = smb + OFF_BUF + b * FBUF_B;
        const uint32_t kaddr = bb + brow * (KSTR * 2) + bcol16;
        const uint32_t vaddr = bb + OFF_VT + brow * (VSTR * 2) + bcol16;

        // ---- S = Q K^T (bf16x3) ----
        float S[8][4];
#pragma unroll
        for (int nt = 0; nt < 8; nt++)
#pragma unroll
            for (int i = 0; i < 4; i++) S[nt][i] = 0.f;

#pragma unroll
        for (int ks = 0; ks < 8; ks++) {
            uint32_t ah[4], al[4];
            ldm4(ah, smb + a_off + ks * 32);
            ldm4(al, smb + OFF_QL + a_off + ks * 32);
#pragma unroll
            for (int ntp = 0; ntp < 4; ntp++) {
                uint32_t bh[4], bl[4];
                ldm4(bh, kaddr + ntp * (16 * KSTR * 2) + ks * 32);
                ldm4(bl, kaddr + KH_B + ntp * (16 * KSTR * 2) + ks * 32);
                mma16816(S[2 * ntp],     ah, bh);
                mma16816(S[2 * ntp + 1], ah, bh + 2);
                mma16816(S[2 * ntp],     ah, bl);
                mma16816(S[2 * ntp + 1], ah, bl + 2);
                mma16816(S[2 * ntp],     al, bh);
                mma16816(S[2 * ntp + 1], al, bh + 2);
            }
        }

        // ---- online softmax (rows r = L>>2 and r+8) ----
        float mx0 = -1e30f, mx1 = -1e30f;
#pragma unroll
        for (int nt = 0; nt < 8; nt++) {
            mx0 = fmaxf(mx0, fmaxf(S[nt][0], S[nt][1]));
            mx1 = fmaxf(mx1, fmaxf(S[nt][2], S[nt][3]));
        }
        mx0 = fmaxf(mx0, __shfl_xor_sync(~0u, mx0, 1));
        mx0 = fmaxf(mx0, __shfl_xor_sync(~0u, mx0, 2));
        mx1 = fmaxf(mx1, __shfl_xor_sync(~0u, mx1, 1));
        mx1 = fmaxf(mx1, __shfl_xor_sync(~0u, mx1, 2));
        const float m0n = fmaxf(m0, mx0), m1n = fmaxf(m1, mx1);
        const float al0 = __expf(m0 - m0n), al1 = __expf(m1 - m1n);
        m0 = m0n; m1 = m1n;
        float rs0 = 0.f, rs1 = 0.f;
#pragma unroll
        for (int nt = 0; nt < 8; nt++) {
            S[nt][0] = __expf(S[nt][0] - m0n); S[nt][1] = __expf(S[nt][1] - m0n);
            S[nt][2] = __expf(S[nt][2] - m1n); S[nt][3] = __expf(S[nt][3] - m1n);
            rs0 += S[nt][0] + S[nt][1];
            rs1 += S[nt][2] + S[nt][3];
        }
        rs0 += __shfl_xor_sync(~0u, rs0, 1); rs0 += __shfl_xor_sync(~0u, rs0, 2);
        rs1 += __shfl_xor_sync(~0u, rs1, 1); rs1 += __shfl_xor_sync(~0u, rs1, 2);
        l0 = l0 * al0 + rs0;
        l1 = l1 * al1 + rs1;
#pragma unroll
        for (int dt = 0; dt < 16; dt++) {
            O[dt][0] *= al0; O[dt][1] *= al0;
            O[dt][2] *= al1; O[dt][3] *= al1;
        }

        // ---- O += P V (P from registers via FA2 layout; bf16x3) ----
#pragma unroll
        for (int ks = 0; ks < 4; ks++) {
            uint32_t ph[4], pl[4];
            pack_hl(S[2 * ks][0],     S[2 * ks][1],     ph[0], pl[0]);
            pack_hl(S[2 * ks][2],     S[2 * ks][3],     ph[1], pl[1]);
            pack_hl(S[2 * ks + 1][0], S[2 * ks + 1][1], ph[2], pl[2]);
            pack_hl(S[2 * ks + 1][2], S[2 * ks + 1][3], ph[3], pl[3]);
#pragma unroll
            for (int dtp = 0; dtp < 8; dtp++) {
                uint32_t bh[4], bl[4];
                ldm4(bh, vaddr + dtp * (16 * VSTR * 2) + ks * 32);
                ldm4(bl, vaddr + VT_B + dtp * (16 * VSTR * 2) + ks * 32);
                mma16816(O[2 * dtp],     ph, bh);
                mma16816(O[2 * dtp + 1], ph, bh + 2);
                mma16816(O[2 * dtp],     ph, bl);
                mma16816(O[2 * dtp + 1], ph, bl + 2);
                mma16816(O[2 * dtp],     pl, bh);
                mma16816(O[2 * dtp + 1], pl, bh + 2);
            }
        }
        __syncthreads();   // protect buffer b before next-iter overwrite
    }

    // ---- finalize: normalize and write bf16 hi/lo ctx split directly ----
    const float inv0 = 1.f / l0, inv1 = 1.f / l1;
    const size_t q = qrow0 + warp * 16 + (L >> 2);
    const size_t base0 = q * DMODEL + h * HDIM + (L & 3) * 2;
#pragma unroll
    for (int dt = 0; dt < 16; dt++) {
        uint32_t h0, l0w, h1, l1w;
        pack_hl(O[dt][0] * inv0, O[dt][1] * inv0, h0, l0w);
        pack_hl(O[dt][2] * inv1, O[dt][3] * inv1, h1, l1w);
        *(uint32_t*)&Ch[base0 + dt * 8] = h0;
        *(uint32_t*)&Cl[base0 + dt * 8] = l0w;
        *(uint32_t*)&Ch[base0 + (size_t)8 * DMODEL + dt * 8] = h1;
        *(uint32_t*)&Cl[base0 + (size_t)8 * DMODEL + dt * 8] = l1w;
    }
}

// ---------------------------------------------------------------------------
__global__ __launch_bounds__(256)
void split_kernel(const float* __restrict__ in, bf16* __restrict__ hi,
                  bf16* __restrict__ lo, float scale, size_t n)
{
    size_t i = ((size_t)blockIdx.x * 256 + threadIdx.x) * 4;
    if (i >= n) return;
    float4 v = *(const float4*)(in + i);
    v.x *= scale; v.y *= scale; v.z *= scale; v.w *= scale;
    bf16 h0 = __float2bfloat16(v.x), h1 = __float2bfloat16(v.y);
    bf16 h2 = __float2bfloat16(v.z), h3 = __float2bfloat16(v.w);
    *(__nv_bfloat162*)(hi + i)     = __halves2bfloat162(h0, h1);
    *(__nv_bfloat162*)(hi + i + 2) = __halves2bfloat162(h2, h3);
    *(__nv_bfloat162*)(lo + i) = __halves2bfloat162(
        __float2bfloat16(v.x - __bfloat162float(h0)),
        __float2bfloat16(v.y - __bfloat162float(h1)));
    *(__nv_bfloat162*)(lo + i + 2) = __halves2bfloat162(
        __float2bfloat16(v.z - __bfloat162float(h2)),
        __float2bfloat16(v.w - __bfloat162float(h3)));
}

__global__ __launch_bounds__(256)
void transpose_split(const float* __restrict__ V, bf16* __restrict__ hi,
                     bf16* __restrict__ lo)
{
    __shared__ float t[32][33];
    const int tx = threadIdx.x & 31, ty = threadIdx.x >> 5;
    const int s0 = blockIdx.x * 32, d0 = blockIdx.y * 32;
#pragma unroll
    for (int j = 0; j < 4; j++)
        t[ty + 8 * j][tx] = V[(size_t)(s0 + ty + 8 * j) * DMODEL + d0 + tx];
    __syncthreads();
#pragma unroll
    for (int j = 0; j < 4; j++) {
        int d = d0 + ty + 8 * j, s = s0 + tx;
        float v = t[tx][ty + 8 * j];
        bf16 hv = __float2bfloat16(v);
        hi[(size_t)d * S_LEN + s] = hv;
        lo[(size_t)d * S_LEN + s] = __float2bfloat16(v - __bfloat162float(hv));
    }
}

// ---------------------------------------------------------------------------
extern "C" void kernel_launch(void* const* d_in, const int* in_sizes, int n_in,
                              void* d_out, int out_size)
{
    (void)in_sizes; (void)n_in; (void)out_size;
    const float* x  = (const float*)d_in[0];
    const float* Wq = (const float*)d_in[1];
    const float* bq = (const float*)d_in[2];
    const float* Wk = (const float*)d_in[3];
    const float* bk = (const float*)d_in[4];
    const float* Wv = (const float*)d_in[5];
    const float* bv = (const float*)d_in[6];
    const float* Wo = (const float*)d_in[7];
    const float* bo = (const float*)d_in[8];
    float* out = (float*)d_out;

    float *Vf;
    bf16 *xh, *xl, *wqh, *wql, *wkh, *wkl, *wvh, *wvl, *woh, *wol;
    bf16 *qh, *ql, *kh, *kl, *vth, *vtl, *ch, *cl;
    cudaGetSymbolAddress((void**)&Vf, g_V);
    cudaGetSymbolAddress((void**)&xh, g_xh);   cudaGetSymbolAddress((void**)&xl, g_xl);
    cudaGetSymbolAddress((void**)&wqh, g_wqh); cudaGetSymbolAddress((void**)&wql, g_wql);
    cudaGetSymbolAddress((void**)&wkh, g_wkh); cudaGetSymbolAddress((void**)&wkl, g_wkl);
    cudaGetSymbolAddress((void**)&wvh, g_wvh); cudaGetSymbolAddress((void**)&wvl, g_wvl);
    cudaGetSymbolAddress((void**)&woh, g_woh); cudaGetSymbolAddress((void**)&wol, g_wol);
    cudaGetSymbolAddress((void**)&qh, g_qh);   cudaGetSymbolAddress((void**)&ql, g_ql);
    cudaGetSymbolAddress((void**)&kh, g_kh);   cudaGetSymbolAddress((void**)&kl, g_kl);
    cudaGetSymbolAddress((void**)&vth, g_vth); cudaGetSymbolAddress((void**)&vtl, g_vtl);
    cudaGetSymbolAddress((void**)&ch, g_ch);   cudaGetSymbolAddress((void**)&cl, g_cl);

    cudaFuncSetAttribute(gemm_bf16x3, cudaFuncAttributeMaxDynamicSharedMemorySize,
                         GEMM_SMEM);
    cudaFuncSetAttribute(flash_attn, cudaFuncAttributeMaxDynamicSharedMemorySize,
                         ATT_SMEM);

    const float qscale = 0.08838834764831845f;   // 1/sqrt(128)

    split_kernel<<<SD / 1024, 256>>>(x,  xh,  xl,  1.f, SD);
    split_kernel<<<DD / 1024, 256>>>(Wq, wqh, wql, 1.f, DD);
    split_kernel<<<DD / 1024, 256>>>(Wk, wkh, wkl, 1.f, DD);
    split_kernel<<<DD / 1024, 256>>>(Wv, wvh, wvl, 1.f, DD);
    split_kernel<<<DD / 1024, 256>>>(Wo, woh, wol, 1.f, DD);

    dim3 gProj(DMODEL / BN, S_LEN / BM);        // (16, 32)
    // Q, K projections: epilogue writes scaled bf16 hi/lo directly
    gemm_bf16x3<<<gProj, 256, GEMM_SMEM>>>(xh, xl, wqh, wql, bq,
                                           nullptr, qh, ql, qscale,
                                           DMODEL, DMODEL, DMODEL, DMODEL);
    gemm_bf16x3<<<gProj, 256, GEMM_SMEM>>>(xh, xl, wkh, wkl, bk,
                                           nullptr, kh, kl, 1.f,
                                           DMODEL, DMODEL, DMODEL, DMODEL);
    // V projection: fp32 (transpose kernel consumes it)
    gemm_bf16x3<<<gProj, 256, GEMM_SMEM>>>(xh, xl, wvh, wvl, bv,
                                           Vf, nullptr, nullptr, 1.f,
                                           DMODEL, DMODEL, DMODEL, DMODEL);
    transpose_split<<<dim3(S_LEN / 32, DMODEL / 32), 256>>>(Vf, vth, vtl);

    // fused attention: scores + softmax + PV -> ctx bf16 hi/lo
    flash_attn<<<dim3(S_LEN / 128, NHEADS), 256, ATT_SMEM>>>(qh, ql, kh, kl,
                                                             vth, vtl, ch, cl);

    // output projection: fp32 + bias
    gemm_bf16x3<<<gProj, 256, GEMM_SMEM>>>(ch, cl, woh, wol, bo,
                                           out, nullptr, nullptr, 1.f,
                                           DMODEL, DMODEL, DMODEL, DMODEL);
}

// round 12
// speedup vs baseline: 3.0897x; 1.0473x over previous
#include <cuda_runtime.h>
#include <cuda_bf16.h>
#include <cstdint>
#include <cstddef>

typedef __nv_bfloat16 bf16;

#define S_LEN  4096
#define DMODEL 2048
#define NHEADS 16
#define HDIM   128

constexpr size_t SD  = (size_t)S_LEN * DMODEL;     // 8,388,608
constexpr size_t DD  = (size_t)DMODEL * DMODEL;    // 4,194,304

// ---------------- static device scratch (no runtime alloc allowed) ----------
__device__ float g_V[SD];
__device__ bf16  g_xh[SD],  g_xl[SD];
__device__ bf16  g_wqh[DD], g_wql[DD], g_wkh[DD], g_wkl[DD];
__device__ bf16  g_wvh[DD], g_wvl[DD], g_woh[DD], g_wol[DD];
__device__ bf16  g_qh[SD],  g_ql[SD];      // Q pre-scaled by 1/sqrt(Hd)
__device__ bf16  g_kh[SD],  g_kl[SD];
__device__ bf16  g_vth[SD], g_vtl[SD];     // V^T  [DMODEL][S_LEN]
__device__ bf16  g_ch[SD],  g_cl[SD];

// ---------------- baseline-PTX helpers (sm_80+, no 'a' features) ------------
__device__ __forceinline__ void cpasync16(uint32_t dst, const void* src) {
    asm volatile("cp.async.cg.shared.global [%0], [%1], 16;" :: "r"(dst), "l"(src));
}
__device__ __forceinline__ void cp_commit() {
    asm volatile("cp.async.commit_group;" ::: "memory");
}
// m16n8k16 row.col bf16 -> fp32 accumulate
__device__ __forceinline__ void mma16816(float* d, const uint32_t* a, const uint32_t* b) {
    asm volatile(
        "mma.sync.aligned.m16n8k16.row.col.f32.bf16.bf16.f32 "
        "{%0,%1,%2,%3}, {%4,%5,%6,%7}, {%8,%9}, {%0,%1,%2,%3};"
        : "+f"(d[0]), "+f"(d[1]), "+f"(d[2]), "+f"(d[3])
        : "r"(a[0]), "r"(a[1]), "r"(a[2]), "r"(a[3]), "r"(b[0]), "r"(b[1]));
}
__device__ __forceinline__ void ldm4(uint32_t* r, uint32_t addr) {
    asm volatile("ldmatrix.sync.aligned.m8n8.x4.shared.b16 {%0,%1,%2,%3}, [%4];"
                 : "=r"(r[0]), "=r"(r[1]), "=r"(r[2]), "=r"(r[3]) : "r"(addr));
}
// pack 2 floats -> bf16x2 hi word, and residual lo word
__device__ __forceinline__ void pack_hl(float x, float y, uint32_t& hi, uint32_t& lo) {
    bf16 hx = __float2bfloat16(x), hy = __float2bfloat16(y);
    __nv_bfloat162 h2 = __halves2bfloat162(hx, hy);
    __nv_bfloat162 l2 = __halves2bfloat162(
        __float2bfloat16(x - __bfloat162float(hx)),
        __float2bfloat16(y - __bfloat162float(hy)));
    hi = *(uint32_t*)&h2;
    lo = *(uint32_t*)&l2;
}

// ---------------------------------------------------------------------------
// bf16x3 GEMM with ldmatrix fragment loads, multi-job (grid.z selects output).
// C = (Ahi+Alo)(Bhi+Blo)^T + bias; fp32 out OR scaled bf16 hi/lo split out.
// BM=128, BN=128, BK=64, 8 warps in 4(m) x 2(n); warp tile 32x64.
// ---------------------------------------------------------------------------
struct GemmJob {
    const bf16* Bh; const bf16* Bl; const float* bias;
    float* Cf32; bf16* Ch; bf16* Cl; float scale;
};

#define BM 128
#define BN 128
#define BK 64
#define ROWE   72                      // 64 + 8 pad (bf16); 144B stride, conflict-free
#define ROWE2  (ROWE * 2)
#define SUB_B  (128 * ROWE2)           // 18432
#define BUF_B  (4 * SUB_B)             // 73728
#define GEMM_SMEM (2 * BUF_B)          // 147456

__global__ __launch_bounds__(256, 1)
void gemm_bf16x3(const bf16* __restrict__ Ahi, const bf16* __restrict__ Alo,
                 GemmJob j0, GemmJob j1, GemmJob j2,
                 int K, int lda, int ldb, int ldc)
{
    extern __shared__ char smc[];
    const int tid = threadIdx.x;
    const int wid = tid >> 5, L = tid & 31;
    const int warp_m = wid & 3, warp_n = wid >> 2;
    const int n0 = blockIdx.x * BN, m0 = blockIdx.y * BM;
    const GemmJob J = (blockIdx.z == 0) ? j0 : (blockIdx.z == 1) ? j1 : j2;

    float acc[2][8][4];
#pragma unroll
    for (int mt = 0; mt < 2; mt++)
#pragma unroll
        for (int nt = 0; nt < 8; nt++)
#pragma unroll
            for (int i = 0; i < 4; i++) acc[mt][nt][i] = 0.f;

    const uint32_t smb = (uint32_t)__cvta_generic_to_shared(smc);
    // one subtile = 128 rows x 8 chunks (64 bf16) = 1024 chunks; 256 thr x 4
    auto load_sub = [&](uint32_t dstbase, const bf16* src, int row0, int ld, int k0) {
#pragma unroll
        for (int i = 0; i < 4; i++) {
            int c = tid + 256 * i;
            int row = c >> 3, col = (c & 7) * 8;
            cpasync16(dstbase + row * ROWE2 + col * 2,
                      src + (size_t)(row0 + row) * ld + k0 + col);
        }
    };
    auto load_tile = [&](int t, int b) {
        uint32_t base = smb + b * BUF_B;
        int k0 = t * BK;
        load_sub(base,             Ahi,  m0, lda, k0);
        load_sub(base + SUB_B,     Alo,  m0, lda, k0);
        load_sub(base + 2 * SUB_B, J.Bh, n0, ldb, k0);
        load_sub(base + 3 * SUB_B, J.Bl, n0, ldb, k0);
        cp_commit();
    };

    // ldmatrix lane addressing (validated in flash_attn)
    const uint32_t arow = (L & 15), acolsel = (L >> 4) * 16;
    const uint32_t brow = (L & 7) + ((L >> 4) & 1) * 8;
    const uint32_t bcol16 = ((L >> 3) & 1) * 16;

    const int T = K / BK;
    load_tile(0, 0);
    for (int t = 0; t < T; t++) {
        const int b = t & 1;
        asm volatile("cp.async.wait_group 0;" ::: "memory");
        __syncthreads();
        if (t + 1 < T) load_tile(t + 1, 1 ^ b);

        const uint32_t base = smb + b * BUF_B;
        const uint32_t aA0 = base + (warp_m * 32 + arow) * ROWE2 + acolsel;
        const uint32_t aA1 = aA0 + 16 * ROWE2;
        const uint32_t bB  = base + 2 * SUB_B
                           + (warp_n * 64 + brow) * ROWE2 + bcol16;

#pragma unroll
        for (int ks = 0; ks < 4; ks++) {
            const uint32_t ko = ks * 32;
            uint32_t ah[2][4], al[2][4];
            ldm4(ah[0], aA0 + ko);
            ldm4(ah[1], aA1 + ko);
            ldm4(al[0], aA0 + SUB_B + ko);
            ldm4(al[1], aA1 + SUB_B + ko);
#pragma unroll
            for (int ntp = 0; ntp < 4; ntp++) {
                uint32_t bh[4], bl[4];
                const uint32_t ba = bB + ntp * (16 * ROWE2) + ko;
                ldm4(bh, ba);
                ldm4(bl, ba + SUB_B);
#pragma unroll
                for (int mt = 0; mt < 2; mt++) {
                    mma16816(acc[mt][2 * ntp],     ah[mt], bh);
                    mma16816(acc[mt][2 * ntp + 1], ah[mt], bh + 2);
                    mma16816(acc[mt][2 * ntp],     ah[mt], bl);
                    mma16816(acc[mt][2 * ntp + 1], ah[mt], bl + 2);
                    mma16816(acc[mt][2 * ntp],     al[mt], bh);
                    mma16816(acc[mt][2 * ntp + 1], al[mt], bh + 2);
                }
            }
        }
        __syncthreads();
    }

    // epilogue: accumulator fragment (r = L>>2, c pairs at (L&3)*2)
    const int gr = L >> 2, kc = (L & 3) * 2;
#pragma unroll
    for (int nt = 0; nt < 8; nt++) {
        const int c = n0 + warp_n * 64 + nt * 8 + kc;
        float2 bv = make_float2(0.f, 0.f);
        if (J.bias) bv = *(const float2*)&J.bias[c];
#pragma unroll
        for (int mt = 0; mt < 2; mt++) {
            const int r = m0 + warp_m * 32 + mt * 16 + gr;
            float x0 = acc[mt][nt][0] + bv.x, y0 = acc[mt][nt][1] + bv.y;
            float x1 = acc[mt][nt][2] + bv.x, y1 = acc[mt][nt][3] + bv.y;
            if (J.Cf32) {
                *(float2*)&J.Cf32[(size_t)r * ldc + c]       = make_float2(x0, y0);
                *(float2*)&J.Cf32[(size_t)(r + 8) * ldc + c] = make_float2(x1, y1);
            } else {
                x0 *= J.scale; y0 *= J.scale; x1 *= J.scale; y1 *= J.scale;
                uint32_t h0, l0, h1, l1;
                pack_hl(x0, y0, h0, l0);
                pack_hl(x1, y1, h1, l1);
                *(uint32_t*)&J.Ch[(size_t)r * ldc + c]       = h0;
                *(uint32_t*)&J.Cl[(size_t)r * ldc + c]       = l0;
                *(uint32_t*)&J.Ch[(size_t)(r + 8) * ldc + c] = h1;
                *(uint32_t*)&J.Cl[(size_t)(r + 8) * ldc + c] = l1;
            }
        }
    }
}

// ---------------------------------------------------------------------------
// Fused flash attention (unchanged R11 core — passing).
// ---------------------------------------------------------------------------
#define QSTR 136                        // bf16 units (272 B)
#define KSTR 136
#define VSTR 72                         // 144 B
#define OFF_QL (128 * QSTR * 2)         // 34816
#define OFF_BUF (2 * OFF_QL)            // 69632
#define KH_B (64 * KSTR * 2)            // 17408
#define VT_B (128 * VSTR * 2)           // 18432
#define OFF_VT (2 * KH_B)               // within buffer: Kh|Kl|VTh|VTl
#define FBUF_B (2 * KH_B + 2 * VT_B)    // 71680
#define ATT_SMEM (OFF_BUF + 2 * FBUF_B) // 212992
#define NIT (S_LEN / 64)

__global__ __launch_bounds__(256, 1)
void flash_attn(const bf16* __restrict__ Qh, const bf16* __restrict__ Ql,
                const bf16* __restrict__ Kh, const bf16* __restrict__ Kl,
                const bf16* __restrict__ VTh, const bf16* __restrict__ VTl,
                bf16* __restrict__ Ch, bf16* __restrict__ Cl)
{
    extern __shared__ char smem[];
    const uint32_t smb = (uint32_t)__cvta_generic_to_shared(smem);
    const int tid = threadIdx.x;
    const int warp = tid >> 5, L = tid & 31;
    const int qb = blockIdx.x, h = blockIdx.y;

    const size_t qrow0 = (size_t)qb * 128;
    auto loadQ = [&]() {
#pragma unroll
        for (int i = 0; i < 8; i++) {
            int c = tid + 256 * i;
            int row = c >> 4, col = c & 15;
            cpasync16(smb + row * (QSTR * 2) + col * 16,
                      Qh + (qrow0 + row) * DMODEL + h * HDIM + col * 8);
        }
#pragma unroll
        for (int i = 0; i < 8; i++) {
            int c = tid + 256 * i;
            int row = c >> 4, col = c & 15;
            cpasync16(smb + OFF_QL + row * (QSTR * 2) + col * 16,
                      Ql + (qrow0 + row) * DMODEL + h * HDIM + col * 8);
        }
    };
    auto loadKV = [&](int it, int b) {
        const uint32_t bb = smb + OFF_BUF + b * FBUF_B;
        const size_t krow0 = (size_t)it * 64;
#pragma unroll
        for (int i = 0; i < 4; i++) {
            int c = tid + 256 * i;
            int row = c >> 4, col = c & 15;
            cpasync16(bb + row * (KSTR * 2) + col * 16,
                      Kh + (krow0 + row) * DMODEL + h * HDIM + col * 8);
        }
#pragma unroll
        for (int i = 0; i < 4; i++) {
            int c = tid + 256 * i;
            int row = c >> 4, col = c & 15;
            cpasync16(bb + KH_B + row * (KSTR * 2) + col * 16,
                      Kl + (krow0 + row) * DMODEL + h * HDIM + col * 8);
        }
#pragma unroll
        for (int i = 0; i < 4; i++) {
            int c = tid + 256 * i;
            int row = c >> 3, col = c & 7;
            cpasync16(bb + OFF_VT + row * (VSTR * 2) + col * 16,
                      VTh + (size_t)(h * HDIM + row) * S_LEN + krow0 + col * 8);
        }
#pragma unroll
        for (int i = 0; i < 4; i++) {
            int c = tid + 256 * i;
            int row = c >> 3, col = c & 7;
            cpasync16(bb + OFF_VT + VT_B + row * (VSTR * 2) + col * 16,
                      VTl + (size_t)(h * HDIM + row) * S_LEN + krow0 + col * 8);
        }
        cp_commit();
    };

    const uint32_t a_off = (warp * 16 + (L & 15)) * (QSTR * 2) + (L >> 4) * 16;
    const uint32_t brow = (L & 7) + ((L >> 4) & 1) * 8;
    const uint32_t bcol16 = ((L >> 3) & 1) * 16;

    float O[16][4];
#pragma unroll
    for (int dt = 0; dt < 16; dt++)
#pragma unroll
        for (int i = 0; i < 4; i++) O[dt][i] = 0.f;
    float m0 = -1e30f, m1 = -1e30f, l0 = 0.f, l1 = 0.f;

    loadQ();
    loadKV(0, 0);

    for (int it = 0; it < NIT; it++) {
        const int b = it & 1;
        if (it + 1 < NIT) loadKV(it + 1, 1 ^ b);
        if (it + 1 < NIT)
            asm volatile("cp.async.wait_group 1;" ::: "memory");
        else
            asm volatile("cp.async.wait_group 0;" ::: "memory");
        __syncthreads();

        const uint32_t bb = smb + OFF_BUF + b * FBUF_B;
        const uint32_t kaddr = bb + brow * (KSTR * 2) + bcol16;
        const uint32_t vaddr = bb + OFF_VT + brow * (VSTR * 2) + bcol16;

        float S[8][4];
#pragma unroll
        for (int nt = 0; nt < 8; nt++)
#pragma unroll
            for (int i = 0; i < 4; i++) S[nt][i] = 0.f;

#pragma unroll
        for (int ks = 0; ks < 8; ks++) {
            uint32_t ah[4], al[4];
            ldm4(ah, smb + a_off + ks * 32);
            ldm4(al, smb + OFF_QL + a_off + ks * 32);
#pragma unroll
            for (int ntp = 0; ntp < 4; ntp++) {
                uint32_t bh[4], bl[4];
                ldm4(bh, kaddr + ntp * (16 * KSTR * 2) + ks * 32);
                ldm4(bl, kaddr + KH_B + ntp * (16 * KSTR * 2) + ks * 32);
                mma16816(S[2 * ntp],     ah, bh);
                mma16816(S[2 * ntp + 1], ah, bh + 2);
                mma16816(S[2 * ntp],     ah, bl);
                mma16816(S[2 * ntp + 1], ah, bl + 2);
                mma16816(S[2 * ntp],     al, bh);
                mma16816(S[2 * ntp + 1], al, bh + 2);
            }
        }

        float mx0 = -1e30f, mx1 = -1e30f;
#pragma unroll
        for (int nt = 0; nt < 8; nt++) {
            mx0 = fmaxf(mx0, fmaxf(S[nt][0], S[nt][1]));
            mx1 = fmaxf(mx1, fmaxf(S[nt][2], S[nt][3]));
        }
        mx0 = fmaxf(mx0, __shfl_xor_sync(~0u, mx0, 1));
        mx0 = fmaxf(mx0, __shfl_xor_sync(~0u, mx0, 2));
        mx1 = fmaxf(mx1, __shfl_xor_sync(~0u, mx1, 1));
        mx1 = fmaxf(mx1, __shfl_xor_sync(~0u, mx1, 2));
        const float m0n = fmaxf(m0, mx0), m1n = fmaxf(m1, mx1);
        const float al0 = __expf(m0 - m0n), al1 = __expf(m1 - m1n);
        m0 = m0n; m1 = m1n;
        float rs0 = 0.f, rs1 = 0.f;
#pragma unroll
        for (int nt = 0; nt < 8; nt++) {
            S[nt][0] = __expf(S[nt][0] - m0n); S[nt][1] = __expf(S[nt][1] - m0n);
            S[nt][2] = __expf(S[nt][2] - m1n); S[nt][3] = __expf(S[nt][3] - m1n);
            rs0 += S[nt][0] + S[nt][1];
            rs1 += S[nt][2] + S[nt][3];
        }
        rs0 += __shfl_xor_sync(~0u, rs0, 1); rs0 += __shfl_xor_sync(~0u, rs0, 2);
        rs1 += __shfl_xor_sync(~0u, rs1, 1); rs1 += __shfl_xor_sync(~0u, rs1, 2);
        l0 = l0 * al0 + rs0;
        l1 = l1 * al1 + rs1;
#pragma unroll
        for (int dt = 0; dt < 16; dt++) {
            O[dt][0] *= al0; O[dt][1] *= al0;
            O[dt][2] *= al1; O[dt][3] *= al1;
        }

#pragma unroll
        for (int ks = 0; ks < 4; ks++) {
            uint32_t ph[4], pl[4];
            pack_hl(S[2 * ks][0],     S[2 * ks][1],     ph[0], pl[0]);
            pack_hl(S[2 * ks][2],     S[2 * ks][3],     ph[1], pl[1]);
            pack_hl(S[2 * ks + 1][0], S[2 * ks + 1][1], ph[2], pl[2]);
            pack_hl(S[2 * ks + 1][2], S[2 * ks + 1][3], ph[3], pl[3]);
#pragma unroll
            for (int dtp = 0; dtp < 8; dtp++) {
                uint32_t bh[4], bl[4];
                ldm4(bh, vaddr + dtp * (16 * VSTR * 2) + ks * 32);
                ldm4(bl, vaddr + VT_B + dtp * (16 * VSTR * 2) + ks * 32);
                mma16816(O[2 * dtp],     ph, bh);
                mma16816(O[2 * dtp + 1], ph, bh + 2);
                mma16816(O[2 * dtp],     ph, bl);
                mma16816(O[2 * dtp + 1], ph, bl + 2);
                mma16816(O[2 * dtp],     pl, bh);
                mma16816(O[2 * dtp + 1], pl, bh + 2);
            }
        }
        __syncthreads();
    }

    const float inv0 = 1.f / l0, inv1 = 1.f / l1;
    const size_t q = qrow0 + warp * 16 + (L >> 2);
    const size_t base0 = q * DMODEL + h * HDIM + (L & 3) * 2;
#pragma unroll
    for (int dt = 0; dt < 16; dt++) {
        uint32_t h0, l0w, h1, l1w;
        pack_hl(O[dt][0] * inv0, O[dt][1] * inv0, h0, l0w);
        pack_hl(O[dt][2] * inv1, O[dt][3] * inv1, h1, l1w);
        *(uint32_t*)&Ch[base0 + dt * 8] = h0;
        *(uint32_t*)&Cl[base0 + dt * 8] = l0w;
        *(uint32_t*)&Ch[base0 + (size_t)8 * DMODEL + dt * 8] = h1;
        *(uint32_t*)&Cl[base0 + (size_t)8 * DMODEL + dt * 8] = l1w;
    }
}

// ---------------------------------------------------------------------------
struct SplitJob { const float* in; bf16* hi; bf16* lo; };

__global__ __launch_bounds__(256)
void split_kernel4(SplitJob s0, SplitJob s1, SplitJob s2, SplitJob s3, size_t n)
{
    const SplitJob S = (blockIdx.y == 0) ? s0 : (blockIdx.y == 1) ? s1
                     : (blockIdx.y == 2) ? s2 : s3;
    size_t i = ((size_t)blockIdx.x * 256 + threadIdx.x) * 4;
    if (i >= n) return;
    float4 v = *(const float4*)(S.in + i);
    bf16 h0 = __float2bfloat16(v.x), h1 = __float2bfloat16(v.y);
    bf16 h2 = __float2bfloat16(v.z), h3 = __float2bfloat16(v.w);
    *(__nv_bfloat162*)(S.hi + i)     = __halves2bfloat162(h0, h1);
    *(__nv_bfloat162*)(S.hi + i + 2) = __halves2bfloat162(h2, h3);
    *(__nv_bfloat162*)(S.lo + i) = __halves2bfloat162(
        __float2bfloat16(v.x - __bfloat162float(h0)),
        __float2bfloat16(v.y - __bfloat162float(h1)));
    *(__nv_bfloat162*)(S.lo + i + 2) = __halves2bfloat162(
        __float2bfloat16(v.z - __bfloat162float(h2)),
        __float2bfloat16(v.w - __bfloat162float(h3)));
}

__global__ __launch_bounds__(256)
void transpose_split(const float* __restrict__ V, bf16* __restrict__ hi,
                     bf16* __restrict__ lo)
{
    __shared__ float t[32][33];
    const int tx = threadIdx.x & 31, ty = threadIdx.x >> 5;
    const int s0 = blockIdx.x * 32, d0 = blockIdx.y * 32;
#pragma unroll
    for (int j = 0; j < 4; j++)
        t[ty + 8 * j][tx] = V[(size_t)(s0 + ty + 8 * j) * DMODEL + d0 + tx];
    __syncthreads();
#pragma unroll
    for (int j = 0; j < 4; j++) {
        int d = d0 + ty + 8 * j, s = s0 + tx;
        float v = t[tx][ty + 8 * j];
        bf16 hv = __float2bfloat16(v);
        hi[(size_t)d * S_LEN + s] = hv;
        lo[(size_t)d * S_LEN + s] = __float2bfloat16(v - __bfloat162float(hv));
    }
}

// ---------------------------------------------------------------------------
extern "C" void kernel_launch(void* const* d_in, const int* in_sizes, int n_in,
                              void* d_out, int out_size)
{
    (void)in_sizes; (void)n_in; (void)out_size;
    const float* x  = (const float*)d_in[0];
    const float* Wq = (const float*)d_in[1];
    const float* bq = (const float*)d_in[2];
    const float* Wk = (const float*)d_in[3];
    const float* bk = (const float*)d_in[4];
    const float* Wv = (const float*)d_in[5];
    const float* bv = (const float*)d_in[6];
    const float* Wo = (const float*)d_in[7];
    const float* bo = (const float*)d_in[8];
    float* out = (float*)d_out;

    float *Vf;
    bf16 *xh, *xl, *wqh, *wql, *wkh, *wkl, *wvh, *wvl, *woh, *wol;
    bf16 *qh, *ql, *kh, *kl, *vth, *vtl, *ch, *cl;
    cudaGetSymbolAddress((void**)&Vf, g_V);
    cudaGetSymbolAddress((void**)&xh, g_xh);   cudaGetSymbolAddress((void**)&xl, g_xl);
    cudaGetSymbolAddress((void**)&wqh, g_wqh); cudaGetSymbolAddress((void**)&wql, g_wql);
    cudaGetSymbolAddress((void**)&wkh, g_wkh); cudaGetSymbolAddress((void**)&wkl, g_wkl);
    cudaGetSymbolAddress((void**)&wvh, g_wvh); cudaGetSymbolAddress((void**)&wvl, g_wvl);
    cudaGetSymbolAddress((void**)&woh, g_woh); cudaGetSymbolAddress((void**)&wol, g_wol);
    cudaGetSymbolAddress((void**)&qh, g_qh);   cudaGetSymbolAddress((void**)&ql, g_ql);
    cudaGetSymbolAddress((void**)&kh, g_kh);   cudaGetSymbolAddress((void**)&kl, g_kl);
    cudaGetSymbolAddress((void**)&vth, g_vth); cudaGetSymbolAddress((void**)&vtl, g_vtl);
    cudaGetSymbolAddress((void**)&ch, g_ch);   cudaGetSymbolAddress((void**)&cl, g_cl);

    cudaFuncSetAttribute(gemm_bf16x3, cudaFuncAttributeMaxDynamicSharedMemorySize,
                         GEMM_SMEM);
    cudaFuncSetAttribute(flash_attn, cudaFuncAttributeMaxDynamicSharedMemorySize,
                         ATT_SMEM);

    const float qscale = 0.08838834764831845f;   // 1/sqrt(128)

    // x split (grid.y=1 padding with same job is harmless but wasteful; use
    // dedicated launch for x, fused launch for the 4 weights)
    {
        SplitJob sx{x, xh, xl};
        split_kernel4<<<dim3(SD / 1024, 1), 256>>>(sx, sx, sx, sx, SD);
        SplitJob s0{Wq, wqh, wql}, s1{Wk, wkh, wkl}, s2{Wv, wvh, wvl}, s3{Wo, woh, wol};
        split_kernel4<<<dim3(DD / 1024, 4), 256>>>(s0, s1, s2, s3, DD);
    }

    // fused Q/K/V projections (grid.z=3)
    {
        GemmJob jq{wqh, wql, bq, nullptr, qh, ql, qscale};
        GemmJob jk{wkh, wkl, bk, nullptr, kh, kl, 1.f};
        GemmJob jv{wvh, wvl, bv, Vf, nullptr, nullptr, 1.f};
        dim3 g(DMODEL / BN, S_LEN / BM, 3);     // (16, 32, 3)
        gemm_bf16x3<<<g, 256, GEMM_SMEM>>>(xh, xl, jq, jk, jv,
                                           DMODEL, DMODEL, DMODEL, DMODEL);
    }
    transpose_split<<<dim3(S_LEN / 32, DMODEL / 32), 256>>>(Vf, vth, vtl);

    // fused attention: scores + softmax + PV -> ctx bf16 hi/lo
    flash_attn<<<dim3(S_LEN / 128, NHEADS), 256, ATT_SMEM>>>(qh, ql, kh, kl,
                                                             vth, vtl, ch, cl);

    // output projection: fp32 + bias
    {
        GemmJob jo{woh, wol, bo, out, nullptr, nullptr, 1.f};
        dim3 g(DMODEL / BN, S_LEN / BM, 1);
        gemm_bf16x3<<<g, 256, GEMM_SMEM>>>(ch, cl, jo, jo, jo,
                                           DMODEL, DMODEL, DMODEL, DMODEL);
    }
}

// round 17
// speedup vs baseline: 3.0924x; 1.0009x over previous
#include <cuda_runtime.h>
#include <cuda_bf16.h>
#include <cstdint>
#include <cstddef>

typedef __nv_bfloat16 bf16;

#define S_LEN  4096
#define DMODEL 2048
#define NHEADS 16
#define HDIM   128

constexpr size_t SD  = (size_t)S_LEN * DMODEL;     // 8,388,608
constexpr size_t DD  = (size_t)DMODEL * DMODEL;    // 4,194,304

// ---------------- static device scratch (no runtime alloc allowed) ----------
__device__ float g_V[SD];
__device__ bf16  g_xh[SD],  g_xl[SD];
__device__ bf16  g_wqh[DD], g_wql[DD], g_wkh[DD], g_wkl[DD];
__device__ bf16  g_wvh[DD], g_wvl[DD], g_woh[DD], g_wol[DD];
__device__ bf16  g_qh[SD],  g_ql[SD];      // Q pre-scaled by 1/sqrt(Hd)
__device__ bf16  g_kh[SD],  g_kl[SD];
__device__ bf16  g_vth[SD], g_vtl[SD];     // V^T  [DMODEL][S_LEN]
__device__ bf16  g_ch[SD],  g_cl[SD];

// ---------------- baseline-PTX helpers (sm_80+, no 'a' features) ------------
__device__ __forceinline__ void cpasync16(uint32_t dst, const void* src) {
    asm volatile("cp.async.cg.shared.global [%0], [%1], 16;" :: "r"(dst), "l"(src));
}
__device__ __forceinline__ void cp_commit() {
    asm volatile("cp.async.commit_group;" ::: "memory");
}
// m16n8k16 row.col bf16 -> fp32 accumulate
__device__ __forceinline__ void mma16816(float* d, const uint32_t* a, const uint32_t* b) {
    asm volatile(
        "mma.sync.aligned.m16n8k16.row.col.f32.bf16.bf16.f32 "
        "{%0,%1,%2,%3}, {%4,%5,%6,%7}, {%8,%9}, {%0,%1,%2,%3};"
        : "+f"(d[0]), "+f"(d[1]), "+f"(d[2]), "+f"(d[3])
        : "r"(a[0]), "r"(a[1]), "r"(a[2]), "r"(a[3]), "r"(b[0]), "r"(b[1]));
}
__device__ __forceinline__ void ldm4(uint32_t* r, uint32_t addr) {
    asm volatile("ldmatrix.sync.aligned.m8n8.x4.shared.b16 {%0,%1,%2,%3}, [%4];"
                 : "=r"(r[0]), "=r"(r[1]), "=r"(r[2]), "=r"(r[3]) : "r"(addr));
}
// pack 2 floats -> bf16x2 hi word, and residual lo word
__device__ __forceinline__ void pack_hl(float x, float y, uint32_t& hi, uint32_t& lo) {
    bf16 hx = __float2bfloat16(x), hy = __float2bfloat16(y);
    __nv_bfloat162 h2 = __halves2bfloat162(hx, hy);
    __nv_bfloat162 l2 = __halves2bfloat162(
        __float2bfloat16(x - __bfloat162float(hx)),
        __float2bfloat16(y - __bfloat162float(hy)));
    hi = *(uint32_t*)&h2;
    lo = *(uint32_t*)&l2;
}

// ---------------------------------------------------------------------------
// bf16x3 GEMM: 3-stage cp.async pipeline, ldmatrix fragments, multi-job.
// C = (Ahi+Alo)(Bhi+Blo)^T + bias; fp32 out OR scaled bf16 hi/lo split out.
// BM=128, BN=128, BK=64, 8 warps in 4(m) x 2(n); warp tile 32x64.
// ---------------------------------------------------------------------------
struct GemmJob {
    const bf16* Bh; const bf16* Bl; const float* bias;
    float* Cf32; bf16* Ch; bf16* Cl; float scale;
};

#define BM 128
#define BN 128
#define BK 64
#define ROWE   72                      // 64 + 8 pad (bf16); 144B stride, conflict-free
#define ROWE2  (ROWE * 2)
#define SUB_B  (128 * ROWE2)           // 18432
#define BUF_B  (4 * SUB_B)             // 73728
#define NSTAGE 3
#define GEMM_SMEM (NSTAGE * BUF_B)     // 221184

__global__ __launch_bounds__(256, 1)
void gemm_bf16x3(const bf16* __restrict__ Ahi, const bf16* __restrict__ Alo,
                 GemmJob j0, GemmJob j1, GemmJob j2,
                 int K, int lda, int ldb, int ldc)
{
    extern __shared__ char smc[];
    const int tid = threadIdx.x;
    const int wid = tid >> 5, L = tid & 31;
    const int warp_m = wid & 3, warp_n = wid >> 2;
    const int n0 = blockIdx.x * BN, m0 = blockIdx.y * BM;
    const GemmJob J = (blockIdx.z == 0) ? j0 : (blockIdx.z == 1) ? j1 : j2;

    float acc[2][8][4];
#pragma unroll
    for (int mt = 0; mt < 2; mt++)
#pragma unroll
        for (int nt = 0; nt < 8; nt++)
#pragma unroll
            for (int i = 0; i < 4; i++) acc[mt][nt][i] = 0.f;

    const uint32_t smb = (uint32_t)__cvta_generic_to_shared(smc);
    // one subtile = 128 rows x 8 chunks (64 bf16) = 1024 chunks; 256 thr x 4
    auto load_sub = [&](uint32_t dstbase, const bf16* src, int row0, int ld, int k0) {
#pragma unroll
        for (int i = 0; i < 4; i++) {
            int c = tid + 256 * i;
            int row = c >> 3, col = (c & 7) * 8;
            cpasync16(dstbase + row * ROWE2 + col * 2,
                      src + (size_t)(row0 + row) * ld + k0 + col);
        }
    };
    auto load_tile = [&](int t, int b) {
        uint32_t base = smb + b * BUF_B;
        int k0 = t * BK;
        load_sub(base,             Ahi,  m0, lda, k0);
        load_sub(base + SUB_B,     Alo,  m0, lda, k0);
        load_sub(base + 2 * SUB_B, J.Bh, n0, ldb, k0);
        load_sub(base + 3 * SUB_B, J.Bl, n0, ldb, k0);
        cp_commit();
    };

    // ldmatrix lane addressing (validated in flash_attn)
    const uint32_t arow = (L & 15), acolsel = (L >> 4) * 16;
    const uint32_t brow = (L & 7) + ((L >> 4) & 1) * 8;
    const uint32_t bcol16 = ((L >> 3) & 1) * 16;

    const int T = K / BK;
    load_tile(0, 0);
    load_tile(1, 1);
    int buf = 0;
    for (int t = 0; t < T; t++) {
        // tile t must be resident; tile t+1 may remain in flight
        if (t + 1 < T)
            asm volatile("cp.async.wait_group 1;" ::: "memory");
        else
            asm volatile("cp.async.wait_group 0;" ::: "memory");
        __syncthreads();   // all warps done with compute(t-1) -> buffer (t+2)%3 free
        if (t + 2 < T) load_tile(t + 2, (t + 2) % NSTAGE);

        const uint32_t base = smb + buf * BUF_B;
        buf = (buf + 1 == NSTAGE) ? 0 : buf + 1;
        const uint32_t aA0 = base + (warp_m * 32 + arow) * ROWE2 + acolsel;
        const uint32_t aA1 = aA0 + 16 * ROWE2;
        const uint32_t bB  = base + 2 * SUB_B
                           + (warp_n * 64 + brow) * ROWE2 + bcol16;

#pragma unroll
        for (int ks = 0; ks < 4; ks++) {
            const uint32_t ko = ks * 32;
            uint32_t ah[2][4], al[2][4];
            ldm4(ah[0], aA0 + ko);
            ldm4(ah[1], aA1 + ko);
            ldm4(al[0], aA0 + SUB_B + ko);
            ldm4(al[1], aA1 + SUB_B + ko);
#pragma unroll
            for (int ntp = 0; ntp < 4; ntp++) {
                uint32_t bh[4], bl[4];
                const uint32_t ba = bB + ntp * (16 * ROWE2) + ko;
                ldm4(bh, ba);
                ldm4(bl, ba + SUB_B);
#pragma unroll
                for (int mt = 0; mt < 2; mt++) {
                    mma16816(acc[mt][2 * ntp],     ah[mt], bh);
                    mma16816(acc[mt][2 * ntp + 1], ah[mt], bh + 2);
                    mma16816(acc[mt][2 * ntp],     ah[mt], bl);
                    mma16816(acc[mt][2 * ntp + 1], ah[mt], bl + 2);
                    mma16816(acc[mt][2 * ntp],     al[mt], bh);
                    mma16816(acc[mt][2 * ntp + 1], al[mt], bh + 2);
                }
            }
        }
    }

    // epilogue: accumulator fragment (r = L>>2, c pairs at (L&3)*2)
    const int gr = L >> 2, kc = (L & 3) * 2;
#pragma unroll
    for (int nt = 0; nt < 8; nt++) {
        const int c = n0 + warp_n * 64 + nt * 8 + kc;
        float2 bv = make_float2(0.f, 0.f);
        if (J.bias) bv = *(const float2*)&J.bias[c];
#pragma unroll
        for (int mt = 0; mt < 2; mt++) {
            const int r = m0 + warp_m * 32 + mt * 16 + gr;
            float x0 = acc[mt][nt][0] + bv.x, y0 = acc[mt][nt][1] + bv.y;
            float x1 = acc[mt][nt][2] + bv.x, y1 = acc[mt][nt][3] + bv.y;
            if (J.Cf32) {
                *(float2*)&J.Cf32[(size_t)r * ldc + c]       = make_float2(x0, y0);
                *(float2*)&J.Cf32[(size_t)(r + 8) * ldc + c] = make_float2(x1, y1);
            } else {
                x0 *= J.scale; y0 *= J.scale; x1 *= J.scale; y1 *= J.scale;
                uint32_t h0, l0, h1, l1;
                pack_hl(x0, y0, h0, l0);
                pack_hl(x1, y1, h1, l1);
                *(uint32_t*)&J.Ch[(size_t)r * ldc + c]       = h0;
                *(uint32_t*)&J.Cl[(size_t)r * ldc + c]       = l0;
                *(uint32_t*)&J.Ch[(size_t)(r + 8) * ldc + c] = h1;
                *(uint32_t*)&J.Cl[(size_t)(r + 8) * ldc + c] = l1;
            }
        }
    }
}

// ---------------------------------------------------------------------------
// Fused flash attention (unchanged R11/R12 core — passing).
// ---------------------------------------------------------------------------
#define QSTR 136                        // bf16 units (272 B)
#define KSTR 136
#define VSTR 72                         // 144 B
#define OFF_QL (128 * QSTR * 2)         // 34816
#define OFF_BUF (2 * OFF_QL)            // 69632
#define KH_B (64 * KSTR * 2)            // 17408
#define VT_B (128 * VSTR * 2)           // 18432
#define OFF_VT (2 * KH_B)               // within buffer: Kh|Kl|VTh|VTl
#define FBUF_B (2 * KH_B + 2 * VT_B)    // 71680
#define ATT_SMEM (OFF_BUF + 2 * FBUF_B) // 212992
#define NIT (S_LEN / 64)

__global__ __launch_bounds__(256, 1)
void flash_attn(const bf16* __restrict__ Qh, const bf16* __restrict__ Ql,
                const bf16* __restrict__ Kh, const bf16* __restrict__ Kl,
                const bf16* __restrict__ VTh, const bf16* __restrict__ VTl,
                bf16* __restrict__ Ch, bf16* __restrict__ Cl)
{
    extern __shared__ char smem[];
    const uint32_t smb = (uint32_t)__cvta_generic_to_shared(smem);
    const int tid = threadIdx.x;
    const int warp = tid >> 5, L = tid & 31;
    const int qb = blockIdx.x, h = blockIdx.y;

    const size_t qrow0 = (size_t)qb * 128;
    auto loadQ = [&]() {
#pragma unroll
        for (int i = 0; i < 8; i++) {
            int c = tid + 256 * i;
            int row = c >> 4, col = c & 15;
            cpasync16(smb + row * (QSTR * 2) + col * 16,
                      Qh + (qrow0 + row) * DMODEL + h * HDIM + col * 8);
        }
#pragma unroll
        for (int i = 0; i < 8; i++) {
            int c = tid + 256 * i;
            int row = c >> 4, col = c & 15;
            cpasync16(smb + OFF_QL + row * (QSTR * 2) + col * 16,
                      Ql + (qrow0 + row) * DMODEL + h * HDIM + col * 8);
        }
    };
    auto loadKV = [&](int it, int b) {
        const uint32_t bb = smb + OFF_BUF + b * FBUF_B;
        const size_t krow0 = (size_t)it * 64;
#pragma unroll
        for (int i = 0; i < 4; i++) {
            int c = tid + 256 * i;
            int row = c >> 4, col = c & 15;
            cpasync16(bb + row * (KSTR * 2) + col * 16,
                      Kh + (krow0 + row) * DMODEL + h * HDIM + col * 8);
        }
#pragma unroll
        for (int i = 0; i < 4; i++) {
            int c = tid + 256 * i;
            int row = c >> 4, col = c & 15;
            cpasync16(bb + KH_B + row * (KSTR * 2) + col * 16,
                      Kl + (krow0 + row) * DMODEL + h * HDIM + col * 8);
        }
#pragma unroll
        for (int i = 0; i < 4; i++) {
            int c = tid + 256 * i;
            int row = c >> 3, col = c & 7;
            cpasync16(bb + OFF_VT + row * (VSTR * 2) + col * 16,
                      VTh + (size_t)(h * HDIM + row) * S_LEN + krow0 + col * 8);
        }
#pragma unroll
        for (int i = 0; i < 4; i++) {
            int c = tid + 256 * i;
            int row = c >> 3, col = c & 7;
            cpasync16(bb + OFF_VT + VT_B + row * (VSTR * 2) + col * 16,
                      VTl + (size_t)(h * HDIM + row) * S_LEN + krow0 + col * 8);
        }
        cp_commit();
    };

    const uint32_t a_off = (warp * 16 + (L & 15)) * (QSTR * 2) + (L >> 4) * 16;
    const uint32_t brow = (L & 7) + ((L >> 4) & 1) * 8;
    const uint32_t bcol16 = ((L >> 3) & 1) * 16;

    float O[16][4];
#pragma unroll
    for (int dt = 0; dt < 16; dt++)
#pragma unroll
        for (int i = 0; i < 4; i++) O[dt][i] = 0.f;
    float m0 = -1e30f, m1 = -1e30f, l0 = 0.f, l1 = 0.f;

    loadQ();
    loadKV(0, 0);

    for (int it = 0; it < NIT; it++) {
        const int b = it & 1;
        if (it + 1 < NIT) loadKV(it + 1, 1 ^ b);
        if (it + 1 < NIT)
            asm volatile("cp.async.wait_group 1;" ::: "memory");
        else
            asm volatile("cp.async.wait_group 0;" ::: "memory");
        __syncthreads();

        const uint32_t bb = smb + OFF_BUF + b * FBUF_B;
        const uint32_t kaddr = bb + brow * (KSTR * 2) + bcol16;
        const uint32_t vaddr = bb + OFF_VT + brow * (VSTR * 2) + bcol16;

        float S[8][4];
#pragma unroll
        for (int nt = 0; nt < 8; nt++)
#pragma unroll
            for (int i = 0; i < 4; i++) S[nt][i] = 0.f;

#pragma unroll
        for (int ks = 0; ks < 8; ks++) {
            uint32_t ah[4], al[4];
            ldm4(ah, smb + a_off + ks * 32);
            ldm4(al, smb + OFF_QL + a_off + ks * 32);
#pragma unroll
            for (int ntp = 0; ntp < 4; ntp++) {
                uint32_t bh[4], bl[4];
                ldm4(bh, kaddr + ntp * (16 * KSTR * 2) + ks * 32);
                ldm4(bl, kaddr + KH_B + ntp * (16 * KSTR * 2) + ks * 32);
                mma16816(S[2 * ntp],     ah, bh);
                mma16816(S[2 * ntp + 1], ah, bh + 2);
                mma16816(S[2 * ntp],     ah, bl);
                mma16816(S[2 * ntp + 1], ah, bl + 2);
                mma16816(S[2 * ntp],     al, bh);
                mma16816(S[2 * ntp + 1], al, bh + 2);
            }
        }

        float mx0 = -1e30f, mx1 = -1e30f;
#pragma unroll
        for (int nt = 0; nt < 8; nt++) {
            mx0 = fmaxf(mx0, fmaxf(S[nt][0], S[nt][1]));
            mx1 = fmaxf(mx1, fmaxf(S[nt][2], S[nt][3]));
        }
        mx0 = fmaxf(mx0, __shfl_xor_sync(~0u, mx0, 1));
        mx0 = fmaxf(mx0, __shfl_xor_sync(~0u, mx0, 2));
        mx1 = fmaxf(mx1, __shfl_xor_sync(~0u, mx1, 1));
        mx1 = fmaxf(mx1, __shfl_xor_sync(~0u, mx1, 2));
        const float m0n = fmaxf(m0, mx0), m1n = fmaxf(m1, mx1);
        const float al0 = __expf(m0 - m0n), al1 = __expf(m1 - m1n);
        m0 = m0n; m1 = m1n;
        float rs0 = 0.f, rs1 = 0.f;
#pragma unroll
        for (int nt = 0; nt < 8; nt++) {
            S[nt][0] = __expf(S[nt][0] - m0n); S[nt][1] = __expf(S[nt][1] - m0n);
            S[nt][2] = __expf(S[nt][2] - m1n); S[nt][3] = __expf(S[nt][3] - m1n);
            rs0 += S[nt][0] + S[nt][1];
            rs1 += S[nt][2] + S[nt][3];
        }
        rs0 += __shfl_xor_sync(~0u, rs0, 1); rs0 += __shfl_xor_sync(~0u, rs0, 2);
        rs1 += __shfl_xor_sync(~0u, rs1, 1); rs1 += __shfl_xor_sync(~0u, rs1, 2);
        l0 = l0 * al0 + rs0;
        l1 = l1 * al1 + rs1;
#pragma unroll
        for (int dt = 0; dt < 16; dt++) {
            O[dt][0] *= al0; O[dt][1] *= al0;
            O[dt][2] *= al1; O[dt][3] *= al1;
        }

#pragma unroll
        for (int ks = 0; ks < 4; ks++) {
            uint32_t ph[4], pl[4];
            pack_hl(S[2 * ks][0],     S[2 * ks][1],     ph[0], pl[0]);
            pack_hl(S[2 * ks][2],     S[2 * ks][3],     ph[1], pl[1]);
            pack_hl(S[2 * ks + 1][0], S[2 * ks + 1][1], ph[2], pl[2]);
            pack_hl(S[2 * ks + 1][2], S[2 * ks + 1][3], ph[3], pl[3]);
#pragma unroll
            for (int dtp = 0; dtp < 8; dtp++) {
                uint32_t bh[4], bl[4];
                ldm4(bh, vaddr + dtp * (16 * VSTR * 2) + ks * 32);
                ldm4(bl, vaddr + VT_B + dtp * (16 * VSTR * 2) + ks * 32);
                mma16816(O[2 * dtp],     ph, bh);
                mma16816(O[2 * dtp + 1], ph, bh + 2);
                mma16816(O[2 * dtp],     ph, bl);
                mma16816(O[2 * dtp + 1], ph, bl + 2);
                mma16816(O[2 * dtp],     pl, bh);
                mma16816(O[2 * dtp + 1], pl, bh + 2);
            }
        }
        __syncthreads();
    }

    const float inv0 = 1.f / l0, inv1 = 1.f / l1;
    const size_t q = qrow0 + warp * 16 + (L >> 2);
    const size_t base0 = q * DMODEL + h * HDIM + (L & 3) * 2;
#pragma unroll
    for (int dt = 0; dt < 16; dt++) {
        uint32_t h0, l0w, h1, l1w;
        pack_hl(O[dt][0] * inv0, O[dt][1] * inv0, h0, l0w);
        pack_hl(O[dt][2] * inv1, O[dt][3] * inv1, h1, l1w);
        *(uint32_t*)&Ch[base0 + dt * 8] = h0;
        *(uint32_t*)&Cl[base0 + dt * 8] = l0w;
        *(uint32_t*)&Ch[base0 + (size_t)8 * DMODEL + dt * 8] = h1;
        *(uint32_t*)&Cl[base0 + (size_t)8 * DMODEL + dt * 8] = l1w;
    }
}

// ---------------------------------------------------------------------------
struct SplitJob { const float* in; bf16* hi; bf16* lo; };

__global__ __launch_bounds__(256)
void split_kernel4(SplitJob s0, SplitJob s1, SplitJob s2, SplitJob s3, size_t n)
{
    const SplitJob S = (blockIdx.y == 0) ? s0 : (blockIdx.y == 1) ? s1
                     : (blockIdx.y == 2) ? s2 : s3;
    size_t i = ((size_t)blockIdx.x * 256 + threadIdx.x) * 4;
    if (i >= n) return;
    float4 v = *(const float4*)(S.in + i);
    bf16 h0 = __float2bfloat16(v.x), h1 = __float2bfloat16(v.y);
    bf16 h2 = __float2bfloat16(v.z), h3 = __float2bfloat16(v.w);
    *(__nv_bfloat162*)(S.hi + i)     = __halves2bfloat162(h0, h1);
    *(__nv_bfloat162*)(S.hi + i + 2) = __halves2bfloat162(h2, h3);
    *(__nv_bfloat162*)(S.lo + i) = __halves2bfloat162(
        __float2bfloat16(v.x - __bfloat162float(h0)),
        __float2bfloat16(v.y - __bfloat162float(h1)));
    *(__nv_bfloat162*)(S.lo + i + 2) = __halves2bfloat162(
        __float2bfloat16(v.z - __bfloat162float(h2)),
        __float2bfloat16(v.w - __bfloat162float(h3)));
}

__global__ __launch_bounds__(256)
void transpose_split(const float* __restrict__ V, bf16* __restrict__ hi,
                     bf16* __restrict__ lo)
{
    __shared__ float t[32][33];
    const int tx = threadIdx.x & 31, ty = threadIdx.x >> 5;
    const int s0 = blockIdx.x * 32, d0 = blockIdx.y * 32;
#pragma unroll
    for (int j = 0; j < 4; j++)
        t[ty + 8 * j][tx] = V[(size_t)(s0 + ty + 8 * j) * DMODEL + d0 + tx];
    __syncthreads();
#pragma unroll
    for (int j = 0; j < 4; j++) {
        int d = d0 + ty + 8 * j, s = s0 + tx;
        float v = t[tx][ty + 8 * j];
        bf16 hv = __float2bfloat16(v);
        hi[(size_t)d * S_LEN + s] = hv;
        lo[(size_t)d * S_LEN + s] = __float2bfloat16(v - __bfloat162float(hv));
    }
}

// ---------------------------------------------------------------------------
extern "C" void kernel_launch(void* const* d_in, const int* in_sizes, int n_in,
                              void* d_out, int out_size)
{
    (void)in_sizes; (void)n_in; (void)out_size;
    const float* x  = (const float*)d_in[0];
    const float* Wq = (const float*)d_in[1];
    const float* bq = (const float*)d_in[2];
    const float* Wk = (const float*)d_in[3];
    const float* bk = (const float*)d_in[4];
    const float* Wv = (const float*)d_in[5];
    const float* bv = (const float*)d_in[6];
    const float* Wo = (const float*)d_in[7];
    const float* bo = (const float*)d_in[8];
    float* out = (float*)d_out;

    float *Vf;
    bf16 *xh, *xl, *wqh, *wql, *wkh, *wkl, *wvh, *wvl, *woh, *wol;
    bf16 *qh, *ql, *kh, *kl, *vth, *vtl, *ch, *cl;
    cudaGetSymbolAddress((void**)&Vf, g_V);
    cudaGetSymbolAddress((void**)&xh, g_xh);   cudaGetSymbolAddress((void**)&xl, g_xl);
    cudaGetSymbolAddress((void**)&wqh, g_wqh); cudaGetSymbolAddress((void**)&wql, g_wql);
    cudaGetSymbolAddress((void**)&wkh, g_wkh); cudaGetSymbolAddress((void**)&wkl, g_wkl);
    cudaGetSymbolAddress((void**)&wvh, g_wvh); cudaGetSymbolAddress((void**)&wvl, g_wvl);
    cudaGetSymbolAddress((void**)&woh, g_woh); cudaGetSymbolAddress((void**)&wol, g_wol);
    cudaGetSymbolAddress((void**)&qh, g_qh);   cudaGetSymbolAddress((void**)&ql, g_ql);
    cudaGetSymbolAddress((void**)&kh, g_kh);   cudaGetSymbolAddress((void**)&kl, g_kl);
    cudaGetSymbolAddress((void**)&vth, g_vth); cudaGetSymbolAddress((void**)&vtl, g_vtl);
    cudaGetSymbolAddress((void**)&ch, g_ch);   cudaGetSymbolAddress((void**)&cl, g_cl);

    cudaFuncSetAttribute(gemm_bf16x3, cudaFuncAttributeMaxDynamicSharedMemorySize,
                         GEMM_SMEM);
    cudaFuncSetAttribute(flash_attn, cudaFuncAttributeMaxDynamicSharedMemorySize,
                         ATT_SMEM);

    const float qscale = 0.08838834764831845f;   // 1/sqrt(128)

    {
        SplitJob sx{x, xh, xl};
        split_kernel4<<<dim3(SD / 1024, 1), 256>>>(sx, sx, sx, sx, SD);
        SplitJob s0{Wq, wqh, wql}, s1{Wk, wkh, wkl}, s2{Wv, wvh, wvl}, s3{Wo, woh, wol};
        split_kernel4<<<dim3(DD / 1024, 4), 256>>>(s0, s1, s2, s3, DD);
    }

    // fused Q/K/V projections (grid.z=3)
    {
        GemmJob jq{wqh, wql, bq, nullptr, qh, ql, qscale};
        GemmJob jk{wkh, wkl, bk, nullptr, kh, kl, 1.f};
        GemmJob jv{wvh, wvl, bv, Vf, nullptr, nullptr, 1.f};
        dim3 g(DMODEL / BN, S_LEN / BM, 3);     // (16, 32, 3)
        gemm_bf16x3<<<g, 256, GEMM_SMEM>>>(xh, xl, jq, jk, jv,
                                           DMODEL, DMODEL, DMODEL, DMODEL);
    }
    transpose_split<<<dim3(S_LEN / 32, DMODEL / 32), 256>>>(Vf, vth, vtl);

    // fused attention: scores + softmax + PV -> ctx bf16 hi/lo
    flash_attn<<<dim3(S_LEN / 128, NHEADS), 256, ATT_SMEM>>>(qh, ql, kh, kl,
                                                             vth, vtl, ch, cl);

    // output projection: fp32 + bias
    {
        GemmJob jo{woh, wol, bo, out, nullptr, nullptr, 1.f};
        dim3 g(DMODEL / BN, S_LEN / BM, 1);
        gemm_bf16x3<<<g, 256, GEMM_SMEM>>>(ch, cl, jo, jo, jo,
                                           DMODEL, DMODEL, DMODEL, DMODEL);
    }
}